// round 12
// baseline (speedup 1.0000x reference)
#include <cuda_runtime.h>
#include <cuda_fp16.h>
#include <mma.h>
#include <cstdint>

using namespace nvcuda;

#define SEQ 2048
#define EMB 2048
#define NB  2
#define NH  16
#define DH  128
#define MTOT (NB*SEQ)   // 4096
#define PLANE ((size_t)MTOT*EMB)

// ---------------- scratch (static device globals) ----------------
__device__ __half g_xh  [MTOT*EMB];
__device__ __half g_wh  [7][EMB*EMB];       // wq,wk,wv,wo,w0,sww,swv (contiguous)
__device__ __half g_qkvh[2][MTOT*EMB];      // plane0: qh [bh,t,d]; 1: kh [bh,s,d]
__device__ __half g_vp  [MTOT*EMB];         // [bh, d, s] (written by QKV epilogue)
__device__ float  g_ctx [MTOT*EMB];         // attention partial A (unnormalized)
__device__ float  g_ctx2[MTOT*EMB];         // attention partial B (rows t>=1024)
__device__ float  g_rsA [NB*NH*SEQ];        // rowsums A
__device__ float  g_rsB [NB*NH*SEQ];        // rowsums B
__device__ __half g_cth [MTOT*EMB];
__device__ float  g_xa  [MTOT*EMB];
__device__ __half g_x2h [MTOT*EMB];
__device__ __half g_hh  [MTOT*EMB];
__device__ __half g_wuh [2][MTOT*EMB];      // plane0: w, plane1: u (fp16)

__device__ __forceinline__ uint32_t smem_u32(const void* p) {
    uint32_t a;
    asm("{ .reg .u64 t; cvta.to.shared.u64 t, %1; cvt.u32.u64 %0, t; }" : "=r"(a) : "l"(p));
    return a;
}

// ---------------- fp16 wmma NT GEMM, 3-stage cp.async ----------------
constexpr int BM = 128, BN = 128, PITCH = 40;          // pitch in halves
constexpr int STG_BYTES   = BM * PITCH * 2;            // 10240 per operand
constexpr int STAGE_BYTES = 2 * STG_BYTES;             // 20480 (A+B)
constexpr int NSTG = 3;
constexpr int SMEM_GEMM   = NSTG * STAGE_BYTES;        // 61440

// OMODE: 0 = fp32 out (opt RES); 1 = half plain out; 2 = QKV combined
//   (z=0 q head-split, z=1 k head-split scaled, z=2 v transposed into Vp)
template<int OMODE, bool RES>
__global__ void __launch_bounds__(256, 2)
gemm_h(int nk,
       const __half* __restrict__ A, int lda, int zRowA,
       const __half* __restrict__ B, int ldb, int zRowB,
       float* __restrict__ C, __half* __restrict__ Ch, int ldc,
       __half* __restrict__ Vp,
       const float* __restrict__ Rres, float alphaA, float alphaB,
       long long sC)
{
    const int bn0 = blockIdx.x * BN;
    const int bm0 = blockIdx.y * BM;
    const int z = blockIdx.z;

    extern __shared__ __align__(128) char smem[];
    const int tid  = threadIdx.x;
    const int wid  = tid >> 5;
    const int lane = tid & 31;
    const int wm = (wid & 3) * 32;
    const int wn = (wid >> 2) * 64;

    const __half* Abase = A + (size_t)(z * zRowA + bm0) * lda;
    const __half* Bbase = B + (size_t)(z * zRowB + bn0) * ldb;
    const long long coff = (long long)z * sC;

    auto load_chunk = [&](int kc) {
        const int st = kc % NSTG;
        char* sA = smem + st * STAGE_BYTES;
        char* sB = sA + STG_BYTES;
        const __half* ag = Abase + kc * 32;
        const __half* bg = Bbase + kc * 32;
        #pragma unroll
        for (int i = 0; i < 2; i++) {            // 512 16B segs per operand
            int idx = i * 256 + tid;
            int row = idx >> 2, seg = idx & 3;
            uint32_t da = smem_u32(sA + row * (PITCH * 2) + seg * 16);
            const __half* srca = ag + (size_t)row * lda + seg * 8;
            asm volatile("cp.async.cg.shared.global [%0], [%1], 16;" :: "r"(da), "l"(srca));
            uint32_t db = smem_u32(sB + row * (PITCH * 2) + seg * 16);
            const __half* srcb = bg + (size_t)row * ldb + seg * 8;
            asm volatile("cp.async.cg.shared.global [%0], [%1], 16;" :: "r"(db), "l"(srcb));
        }
        asm volatile("cp.async.commit_group;" ::: "memory");
    };

    wmma::fragment<wmma::accumulator, 16, 16, 16, float> acc[2][4];
    #pragma unroll
    for (int mi = 0; mi < 2; mi++)
        #pragma unroll
        for (int ni = 0; ni < 4; ni++) {
            if (RES)
                wmma::load_matrix_sync(acc[mi][ni],
                    Rres + coff + (long long)(bm0 + wm + mi * 16) * ldc + (bn0 + wn + ni * 16),
                    ldc, wmma::mem_row_major);
            else
                wmma::fill_fragment(acc[mi][ni], 0.0f);
        }

    load_chunk(0);
    if (nk > 1) load_chunk(1);

    for (int kc = 0; kc < nk; kc++) {
        if (kc + 1 < nk)
            asm volatile("cp.async.wait_group 1;" ::: "memory");
        else
            asm volatile("cp.async.wait_group 0;" ::: "memory");
        __syncthreads();                          // single sync per chunk
        if (kc + 2 < nk) load_chunk(kc + 2);

        const __half* sA = (const __half*)(smem + (kc % NSTG) * STAGE_BYTES);
        const __half* sB = sA + BM * PITCH;
        #pragma unroll
        for (int kk = 0; kk < 2; kk++) {
            wmma::fragment<wmma::matrix_a, 16, 16, 16, __half, wmma::row_major> af[2];
            #pragma unroll
            for (int mi = 0; mi < 2; mi++)
                wmma::load_matrix_sync(af[mi], sA + (wm + mi * 16) * PITCH + kk * 16, PITCH);
            #pragma unroll
            for (int nh = 0; nh < 2; nh++) {
                wmma::fragment<wmma::matrix_b, 16, 16, 16, __half, wmma::col_major> bf[2];
                #pragma unroll
                for (int j = 0; j < 2; j++)
                    wmma::load_matrix_sync(bf[j], sB + (wn + (nh * 2 + j) * 16) * PITCH + kk * 16, PITCH);
                #pragma unroll
                for (int mi = 0; mi < 2; mi++)
                    #pragma unroll
                    for (int j = 0; j < 2; j++)
                        wmma::mma_sync(acc[mi][nh * 2 + j], af[mi], bf[j], acc[mi][nh * 2 + j]);
            }
        }
    }

    const float alpha = (OMODE == 2) ? ((z == 1) ? alphaB : alphaA) : alphaA;
    if (alpha != 1.0f) {
        #pragma unroll
        for (int mi = 0; mi < 2; mi++)
            #pragma unroll
            for (int ni = 0; ni < 4; ni++)
                #pragma unroll
                for (int e = 0; e < acc[mi][ni].num_elements; e++)
                    acc[mi][ni].x[e] *= alpha;
    }

    if (OMODE == 0) {
        float* Cp = C + coff;
        #pragma unroll
        for (int mi = 0; mi < 2; mi++)
            #pragma unroll
            for (int ni = 0; ni < 4; ni++)
                wmma::store_matrix_sync(
                    Cp + (long long)(bm0 + wm + mi * 16) * ldc + (bn0 + wn + ni * 16),
                    acc[mi][ni], ldc, wmma::mem_row_major);
    } else {
        __syncthreads();                          // all MMAs done before smem reuse
        float* stg = (float*)smem + wid * 320;    // 16x16 tile, pitch 20 (mult of 4)
        __half* Cp = (OMODE == 2) ? (Ch + (size_t)z * PLANE) : Ch;
        const bool vmode = (OMODE == 2) && (z == 2);
        #pragma unroll
        for (int mi = 0; mi < 2; mi++)
            #pragma unroll
            for (int ni = 0; ni < 4; ni++) {
                wmma::store_matrix_sync(stg, acc[mi][ni], 20, wmma::mem_row_major);
                __syncwarp();
                if (vmode) {
                    // tile = 16 tokens x 16 heads at fixed d; transpose to vp[bh][d][s]
                    const int c  = lane >> 1;      // head within tile
                    const int hf = lane & 1;       // token half (8 each)
                    __half hv8[8];
                    #pragma unroll
                    for (int rr = 0; rr < 8; rr++)
                        hv8[rr] = __float2half_rn(stg[(hf * 8 + rr) * 20 + c]);
                    const int grow0 = bm0 + wm + mi * 16;
                    const int bb = grow0 >> 11, t0 = grow0 & 2047;
                    const int d = (bn0 + wn + ni * 16) >> 4;
                    __half* dstv = Vp + ((size_t)((bb << 4) + c) * DH + d) * SEQ + t0 + hf * 8;
                    *reinterpret_cast<uint4*>(dstv) = *reinterpret_cast<uint4*>(hv8);
                } else {
                    const int r  = lane >> 1;
                    const int cb = (lane & 1) * 8;
                    __half2 hv[4];
                    #pragma unroll
                    for (int j = 0; j < 4; j++)
                        hv[j] = __floats2half2_rn(stg[r * 20 + cb + 2 * j],
                                                  stg[r * 20 + cb + 2 * j + 1]);
                    const int grow = bm0 + wm + mi * 16 + r;
                    const int gcol = wn + ni * 16 + cb;
                    __half* dst;
                    if (OMODE == 2) {              // q/k head-split [bh, t, d]
                        const int b = grow >> 11, tt = grow & 2047;
                        dst = Cp + ((size_t)((b << 4) + (bn0 >> 7)) * SEQ + tt) * DH + gcol;
                    } else {
                        dst = Cp + coff + (size_t)grow * ldc + bn0 + gcol;
                    }
                    *reinterpret_cast<uint4*>(dst) = *reinterpret_cast<uint4*>(hv);
                }
                __syncwarp();
            }
    }
}

// ------ fused flash attention, q-tile 128 x k-tile 64, occ 2, k-split ------
// Heavy q-tiles (qt>=8) split into two CTAs over disjoint key ranges; half-1
// writes unnormalized partials to ctxB/rsB, everything else to ctxA/rsA.
// layernorm_h combines (sums add linearly since softmax has no max-sub).
constexpr int AQP = 136;                       // Q/K pitch (halves)
constexpr int AVP = 72;                        // V pitch (halves)
constexpr int ASP = 68;                        // S pitch (floats)
constexpr int APP = 136;                       // P pitch (halves, overlays S)
constexpr int OFF_K = 128 * AQP * 2;           // 34816 (after Q)
constexpr int OFF_V = OFF_K + 64 * AQP * 2;    // 52224
constexpr int OFF_S = OFF_V + 128 * AVP * 2;   // 70656
constexpr int OFF_R = OFF_S + 128 * ASP * 4;   // 105472
constexpr int SMEM_ATT = OFF_R + 128 * 4;      // 105984

// 24 jobs, ordered heavy-first (work = k-iters): qt>=8 split into halves.
__device__ __constant__ int c_job_qt[24] =
    {15,15,7,14,14,13,13,6,12,12,5,11,11,10,10,4,9,9,8,8,3,2,1,0};
__device__ __constant__ int c_job_hf[24] =
    {0,1,-1,0,1,0,1,-1,0,1,-1,0,1,0,1,-1,0,1,0,1,-1,-1,-1,-1};

__global__ void __launch_bounds__(256, 2)
attn_fused128(const __half* __restrict__ qh,   // [bh, t, d]
              const __half* __restrict__ kh,   // [bh, s, d] (pre-scaled)
              const __half* __restrict__ vp,   // [bh, d, s]
              float* __restrict__ ctxA, float* __restrict__ ctxB,
              float* __restrict__ rsA,  float* __restrict__ rsB)
{
    extern __shared__ __align__(128) char smem[];
    __half* Qs = (__half*)smem;
    __half* Ks = (__half*)(smem + OFF_K);
    __half* Vs = (__half*)(smem + OFF_V);
    float*  Ss = (float*)(smem + OFF_S);
    __half* Ps = (__half*)(smem + OFF_S);      // P overlays S (reg-staged, warp-fenced)
    float*  rowsum = (float*)(smem + OFF_R);
    float*  Os = (float*)smem;                 // final O staging overlays Q/K/V

    const int bh  = blockIdx.x & 31;
    const int job = blockIdx.x >> 5;           // heavy jobs first
    const int qt  = c_job_qt[job];
    const int hf  = c_job_hf[job];
    const int b = bh >> 4, h = bh & 15;
    const int tid = threadIdx.x;
    const int wid = tid >> 5;
    const int wm = (wid & 3) * 32;             // QK warp rows (q)
    const int wn = (wid >> 2) * 32;            // QK warp cols (k)
    const int on = (wid >> 2) * 64;            // PV warp cols (d)

    const int nkt = 2 * qt + 2;
    const int kt0 = (hf == 1) ? (nkt >> 1) : 0;
    const int kt1 = (hf == 0) ? (nkt >> 1) : nkt;

    // K tile load (no commit) — 64 x 128 halves
    auto load_k_body = [&](int kt) {
        const __half* kg = kh + ((size_t)bh * SEQ + kt * 64) * DH;
        #pragma unroll
        for (int i = 0; i < 4; i++) {
            int s = i * 256 + tid;
            int row = s >> 4, seg = s & 15;
            uint32_t dk = smem_u32(Ks + row * AQP + seg * 8);
            asm volatile("cp.async.cg.shared.global [%0], [%1], 16;"
                         :: "r"(dk), "l"(kg + (size_t)row * DH + seg * 8));
        }
    };
    // V tile load (no commit) — 128 x 64 halves
    auto load_v_body = [&](int kt) {
        const __half* vg = vp + (size_t)bh * DH * SEQ + kt * 64;
        #pragma unroll
        for (int i = 0; i < 4; i++) {
            int s = i * 256 + tid;
            int row = s >> 3, seg = s & 7;
            uint32_t dv = smem_u32(Vs + row * AVP + seg * 8);
            asm volatile("cp.async.cg.shared.global [%0], [%1], 16;"
                         :: "r"(dv), "l"(vg + (size_t)row * SEQ + seg * 8));
        }
    };

    // prologue group 1: Q tile + K(kt0)
    {
        const __half* qg = qh + ((size_t)bh * SEQ + qt * 128) * DH;
        #pragma unroll
        for (int i = 0; i < 8; i++) {
            int s = i * 256 + tid;
            int row = s >> 4, seg = s & 15;
            uint32_t dst = smem_u32(Qs + row * AQP + seg * 8);
            asm volatile("cp.async.cg.shared.global [%0], [%1], 16;"
                         :: "r"(dst), "l"(qg + (size_t)row * DH + seg * 8));
        }
        load_k_body(kt0);
        asm volatile("cp.async.commit_group;" ::: "memory");
    }
    // prologue group 2: V(kt0)
    load_v_body(kt0);
    asm volatile("cp.async.commit_group;" ::: "memory");

    if (tid < 128) rowsum[tid] = 0.0f;

    wmma::fragment<wmma::accumulator, 16, 16, 16, float> oacc[2][4];
    #pragma unroll
    for (int mi = 0; mi < 2; mi++)
        #pragma unroll
        for (int j = 0; j < 4; j++) wmma::fill_fragment(oacc[mi][j], 0.0f);

    for (int kt = kt0; kt < kt1; kt++) {
        asm volatile("cp.async.wait_group 1;" ::: "memory");   // K(kt) (+Q) arrived
        __syncthreads();

        // S = Q @ K^T  (128x64), warp tile 32x32
        {
            wmma::fragment<wmma::accumulator, 16, 16, 16, float> sacc[2][2];
            #pragma unroll
            for (int mi = 0; mi < 2; mi++)
                #pragma unroll
                for (int j = 0; j < 2; j++) wmma::fill_fragment(sacc[mi][j], 0.0f);
            #pragma unroll
            for (int kk = 0; kk < 8; kk++) {
                wmma::fragment<wmma::matrix_a, 16, 16, 16, __half, wmma::row_major> af[2];
                #pragma unroll
                for (int mi = 0; mi < 2; mi++)
                    wmma::load_matrix_sync(af[mi], Qs + (wm + mi * 16) * AQP + kk * 16, AQP);
                #pragma unroll
                for (int j = 0; j < 2; j++) {
                    wmma::fragment<wmma::matrix_b, 16, 16, 16, __half, wmma::col_major> bf;
                    wmma::load_matrix_sync(bf, Ks + (wn + j * 16) * AQP + kk * 16, AQP);
                    #pragma unroll
                    for (int mi = 0; mi < 2; mi++)
                        wmma::mma_sync(sacc[mi][j], af[mi], bf, sacc[mi][j]);
                }
            }
            #pragma unroll
            for (int mi = 0; mi < 2; mi++)
                #pragma unroll
                for (int j = 0; j < 2; j++)
                    wmma::store_matrix_sync(Ss + (wm + mi * 16) * ASP + wn + j * 16,
                                            sacc[mi][j], ASP, wmma::mem_row_major);
        }
        __syncthreads();                          // QK done: Ks reusable, S visible

        if (kt + 1 < kt1) load_k_body(kt + 1);    // prefetch K (possibly empty group)
        asm volatile("cp.async.commit_group;" ::: "memory");

        // exp (no max-sub) + causal mask; P overlays S: reg-stage, warp fence, write
        {
            const int row = tid >> 1;
            const int c0 = (tid & 1) * 32;
            const bool diag = (kt >= 2 * qt);
            const float* srow = Ss + row * ASP + c0;
            float4 f[8];
            #pragma unroll
            for (int j = 0; j < 8; j++) f[j] = *reinterpret_cast<const float4*>(srow + 4 * j);
            __syncwarp();                        // warp reads done before overlay writes
            const int t = qt * 128 + row;
            const int cbase = kt * 64 + c0;
            float part = 0.0f;
            __half hv[32];
            #pragma unroll
            for (int j = 0; j < 8; j++) {
                float e0 = (diag && cbase + 4 * j + 0 > t) ? 0.0f : __expf(f[j].x);
                float e1 = (diag && cbase + 4 * j + 1 > t) ? 0.0f : __expf(f[j].y);
                float e2 = (diag && cbase + 4 * j + 2 > t) ? 0.0f : __expf(f[j].z);
                float e3 = (diag && cbase + 4 * j + 3 > t) ? 0.0f : __expf(f[j].w);
                part += (e0 + e1) + (e2 + e3);
                hv[4 * j + 0] = __float2half_rn(e0);
                hv[4 * j + 1] = __float2half_rn(e1);
                hv[4 * j + 2] = __float2half_rn(e2);
                hv[4 * j + 3] = __float2half_rn(e3);
            }
            __half* prow = Ps + row * APP + c0;
            #pragma unroll
            for (int j = 0; j < 4; j++)
                *reinterpret_cast<uint4*>(prow + 8 * j) = *reinterpret_cast<uint4*>(hv + 8 * j);
            part += __shfl_xor_sync(0xffffffffu, part, 1);
            if ((tid & 1) == 0) rowsum[row] += part;
        }

        asm volatile("cp.async.wait_group 1;" ::: "memory");   // V(kt) arrived
        __syncthreads();                          // P visible + V visible

        // O += P @ V^T  (V stored [d, s]: col_major B with k = s = 64), warp 32x64
        #pragma unroll
        for (int kk = 0; kk < 4; kk++) {
            wmma::fragment<wmma::matrix_a, 16, 16, 16, __half, wmma::row_major> af[2];
            #pragma unroll
            for (int mi = 0; mi < 2; mi++)
                wmma::load_matrix_sync(af[mi], Ps + (wm + mi * 16) * APP + kk * 16, APP);
            #pragma unroll
            for (int j = 0; j < 4; j++) {
                wmma::fragment<wmma::matrix_b, 16, 16, 16, __half, wmma::col_major> bf;
                wmma::load_matrix_sync(bf, Vs + (on + j * 16) * AVP + kk * 16, AVP);
                #pragma unroll
                for (int mi = 0; mi < 2; mi++)
                    wmma::mma_sync(oacc[mi][j], af[mi], bf, oacc[mi][j]);
            }
        }
        __syncthreads();                          // PV done: Vs/Ps reusable

        if (kt + 1 < kt1) load_v_body(kt + 1);    // prefetch V
        asm volatile("cp.async.commit_group;" ::: "memory");
    }

    // stage O (128x128 fp32, pitch 132), write UNNORMALIZED partials + rowsums
    float* ctxo = (hf == 1) ? ctxB : ctxA;
    float* rso  = (hf == 1) ? rsB  : rsA;
    #pragma unroll
    for (int mi = 0; mi < 2; mi++)
        #pragma unroll
        for (int j = 0; j < 4; j++)
            wmma::store_matrix_sync(Os + (wm + mi * 16) * 132 + on + j * 16,
                                    oacc[mi][j], 132, wmma::mem_row_major);
    __syncthreads();
    {
        const int row = tid >> 1;
        const int c0 = (tid & 1) * 64;
        const int t = qt * 128 + row;
        float* dst = ctxo + ((size_t)(b * SEQ + t)) * EMB + h * DH + c0;
        const float* srow = Os + row * 132 + c0;
        #pragma unroll
        for (int c = 0; c < 64; c += 4)
            *reinterpret_cast<float4*>(dst + c) = *reinterpret_cast<const float4*>(srow + c);
        if (tid < 128)
            rso[(size_t)bh * SEQ + qt * 128 + tid] = rowsum[tid];
    }
}

// ---------------- block reductions ----------------
__device__ __forceinline__ float blk_sum(float v) {
    __shared__ float sh_s[32];
    __shared__ float tot_s;
    int lane = threadIdx.x & 31, w = threadIdx.x >> 5;
    #pragma unroll
    for (int o = 16; o; o >>= 1) v += __shfl_xor_sync(0xffffffffu, v, o);
    if (lane == 0) sh_s[w] = v;
    __syncthreads();
    if (threadIdx.x == 0) {
        float r = 0.f; int nw = blockDim.x >> 5;
        for (int i = 0; i < nw; i++) r += sh_s[i];
        tot_s = r;
    }
    __syncthreads();
    float r = tot_s;
    __syncthreads();
    return r;
}

// ---------------- conversions / norms ----------------
__global__ void f2h_k(const float* __restrict__ in, __half* __restrict__ out) {
    int i = (blockIdx.x * blockDim.x + threadIdx.x) * 4;
    float4 v = *reinterpret_cast<const float4*>(in + i);
    __half2 h[2];
    h[0] = __floats2half2_rn(v.x, v.y);
    h[1] = __floats2half2_rn(v.z, v.w);
    *reinterpret_cast<uint2*>(out + i) = *reinterpret_cast<uint2*>(h);
}

struct W7 { const float* p[7]; };
__global__ void f2h7_k(W7 ws, __half* __restrict__ out) {
    const int plane = blockIdx.y;
    const float* in = ws.p[plane];
    __half* o = out + (size_t)plane * EMB * EMB;
    int i = (blockIdx.x * blockDim.x + threadIdx.x) * 4;
    float4 v = *reinterpret_cast<const float4*>(in + i);
    __half2 h[2];
    h[0] = __floats2half2_rn(v.x, v.y);
    h[1] = __floats2half2_rn(v.z, v.w);
    *reinterpret_cast<uint2*>(o + i) = *reinterpret_cast<uint2*>(h);
}

// layernorm over combined attention partials: ctx = (A [+B]) / (rsA [+rsB])
__global__ void layernorm_h(const float* __restrict__ ctxA, const float* __restrict__ ctxB,
                            const float* __restrict__ rsA, const float* __restrict__ rsB,
                            __half* __restrict__ out,
                            const float* __restrict__ g, const float* __restrict__ b) {
    const size_t r = blockIdx.x;
    const int bb = (int)(r >> 11), t = (int)(r & 2047);
    const bool split = (t >= 1024);              // qt>=8 rows have two partials
    const float* rowA = ctxA + r * EMB;
    const float* rowB = ctxB + r * EMB;
    __half* orow = out + r * EMB;
    __shared__ float buf[EMB];
    __shared__ float inv_s[16];
    if (threadIdx.x < 16) {
        size_t ri = ((size_t)((bb << 4) + threadIdx.x)) * SEQ + t;
        float rs = rsA[ri];
        if (split) rs += rsB[ri];
        inv_s[threadIdx.x] = 1.0f / rs;
    }
    __syncthreads();
    float s = 0.f;
    for (int i = threadIdx.x; i < EMB; i += blockDim.x) {
        float v = rowA[i];
        if (split) v += rowB[i];
        v *= inv_s[i >> 7];
        buf[i] = v; s += v;
    }
    const float mu = blk_sum(s) * (1.0f / EMB);
    float sq = 0.f;
    for (int i = threadIdx.x; i < EMB; i += blockDim.x) { float d = buf[i] - mu; sq += d * d; }
    const float var = blk_sum(sq) * (1.0f / EMB);
    const float inv = rsqrtf(var + 1e-5f);
    for (int i = threadIdx.x; i < EMB; i += blockDim.x)
        orow[i] = __float2half_rn((buf[i] - mu) * inv * g[i] + b[i]);
}

// x := rmsnorm(x) (fp32, residual base) and xh := half(x)
__global__ void rmsnorm_dual(float* __restrict__ x, __half* __restrict__ xh,
                             const float* __restrict__ g) {
    float* row = x + (size_t)blockIdx.x * EMB;
    __half* orow = xh + (size_t)blockIdx.x * EMB;
    __shared__ float buf[EMB];
    float ss = 0.f;
    for (int i = threadIdx.x; i < EMB; i += blockDim.x) { float v = row[i]; buf[i] = v; ss += v * v; }
    ss = blk_sum(ss);
    const float sc = rsqrtf(ss * (1.0f / EMB) + 1e-6f);
    for (int i = threadIdx.x; i < EMB; i += blockDim.x) {
        float r = g[i] * buf[i] * sc;
        row[i] = r;
        orow[i] = __float2half_rn(r);
    }
}

// out = x2 + mlp_rms_g * g * rsqrt(mean(g^2)+eps),  g = w*sigmoid(beta*w)*u  (half w,u)
__global__ void final_k(const float* __restrict__ x2, const __half* __restrict__ wv,
                        const __half* __restrict__ uv, const float* __restrict__ beta,
                        const float* __restrict__ gamma, float* __restrict__ out) {
    const size_t r = blockIdx.x;
    const float bet = beta[0];
    const __half* wrow = wv + r * EMB;
    const __half* urow = uv + r * EMB;
    __shared__ float buf[EMB];
    float ss = 0.f;
    for (int i = threadIdx.x; i < EMB; i += blockDim.x) {
        float wq = __half2float(wrow[i]);
        float s = 1.0f / (1.0f + __expf(-bet * wq));
        float gq = wq * s * __half2float(urow[i]);
        buf[i] = gq; ss += gq * gq;
    }
    ss = blk_sum(ss);
    const float sc = rsqrtf(ss * (1.0f / EMB) + 1e-6f);
    for (int i = threadIdx.x; i < EMB; i += blockDim.x)
        out[r * EMB + i] = x2[r * EMB + i] + gamma[i] * buf[i] * sc;
}

// ---------------- launcher ----------------
extern "C" void kernel_launch(void* const* d_in, const int* in_sizes, int n_in,
                              void* d_out, int out_size) {
    const float* x     = (const float*)d_in[0];
    const float* Wq    = (const float*)d_in[1];
    const float* Wk    = (const float*)d_in[2];
    const float* Wv    = (const float*)d_in[3];
    const float* Wo    = (const float*)d_in[4];
    const float* ln_g  = (const float*)d_in[5];
    const float* ln_b  = (const float*)d_in[6];
    const float* rms_g = (const float*)d_in[7];
    const float* W0    = (const float*)d_in[8];
    const float* swW   = (const float*)d_in[9];
    const float* swV   = (const float*)d_in[10];
    const float* swb   = (const float*)d_in[11];
    const float* mrg   = (const float*)d_in[12];
    float* out = (float*)d_out;

    __half *xh, *wh, *qkv, *vp, *cth, *x2h, *hh, *wuh;
    float *ctxA, *ctxB, *rsA, *rsB, *xa;
    cudaGetSymbolAddress((void**)&xh,   g_xh);
    cudaGetSymbolAddress((void**)&wh,   g_wh);
    cudaGetSymbolAddress((void**)&qkv,  g_qkvh);
    cudaGetSymbolAddress((void**)&vp,   g_vp);
    cudaGetSymbolAddress((void**)&ctxA, g_ctx);
    cudaGetSymbolAddress((void**)&ctxB, g_ctx2);
    cudaGetSymbolAddress((void**)&rsA,  g_rsA);
    cudaGetSymbolAddress((void**)&rsB,  g_rsB);
    cudaGetSymbolAddress((void**)&cth,  g_cth);
    cudaGetSymbolAddress((void**)&xa,   g_xa);
    cudaGetSymbolAddress((void**)&x2h,  g_x2h);
    cudaGetSymbolAddress((void**)&hh,   g_hh);
    cudaGetSymbolAddress((void**)&wuh,  g_wuh);

    __half* qh = qkv + 0 * PLANE;
    __half* kh = qkv + 1 * PLANE;
    __half* wvh = wuh + 0 * PLANE;
    __half* uvh = wuh + 1 * PLANE;
    const long long NW = (long long)EMB * EMB;

    cudaFuncSetAttribute(gemm_h<2,false>, cudaFuncAttributeMaxDynamicSharedMemorySize, SMEM_GEMM);
    cudaFuncSetAttribute(gemm_h<0,true >, cudaFuncAttributeMaxDynamicSharedMemorySize, SMEM_GEMM);
    cudaFuncSetAttribute(gemm_h<1,false>, cudaFuncAttributeMaxDynamicSharedMemorySize, SMEM_GEMM);
    cudaFuncSetAttribute(attn_fused128,   cudaFuncAttributeMaxDynamicSharedMemorySize, SMEM_ATT);

    const float scale = 0.08838834764831845f;  // 1/sqrt(128)
    const int NEW = MTOT * EMB;                // 8,388,608
    dim3 blk(256);

    // fp32 -> fp16 operand conversions
    f2h_k<<<NEW / 1024, 256>>>(x, xh);
    W7 ws; ws.p[0]=Wq; ws.p[1]=Wk; ws.p[2]=Wv; ws.p[3]=Wo; ws.p[4]=W0; ws.p[5]=swW; ws.p[6]=swV;
    f2h7_k<<<dim3(NW / 1024, 7), 256>>>(ws, wh);

    // merged QKV projection: z=0 q head-split, z=1 k scaled head-split,
    // z=2 v transposed straight into vp (repack fused)
    dim3 gqkv(EMB / BN, MTOT / BM, 3);         // (16,32,3)
    gemm_h<2,false><<<gqkv, blk, SMEM_GEMM>>>(64,
        xh, EMB, 0, wh, EMB, EMB, nullptr, qkv, EMB, vp, nullptr, 1.0f, scale, 0);

    // fused attention with k-split load balancing (768 CTAs, heavy-first)
    attn_fused128<<<768, blk, SMEM_ATT>>>(qh, kh, vp, ctxA, ctxB, rsA, rsB);

    layernorm_h<<<MTOT, 256>>>(ctxA, ctxB, rsA, rsB, cth, ln_g, ln_b);

    // xa = x + cth @ Wo^T (fp32, residual fused via accumulator init)
    dim3 gp(EMB / BN, MTOT / BM, 1);           // (16,32,1)
    gemm_h<0,true><<<gp, blk, SMEM_GEMM>>>(64,
        cth, EMB, 0, wh + 3 * NW, EMB, 0, xa, nullptr, EMB, nullptr, x, 1.0f, 1.0f, 0);

    rmsnorm_dual<<<MTOT, 256>>>(xa, x2h, rms_g);

    // h = x2 @ W0^T (half out)
    gemm_h<1,false><<<gp, blk, SMEM_GEMM>>>(64,
        x2h, EMB, 0, wh + 4 * NW, EMB, 0, nullptr, hh, EMB, nullptr, nullptr, 1.0f, 1.0f, 0);

    // merged swW/swV: z selects weight plane + half output plane
    dim3 gsw(EMB / BN, MTOT / BM, 2);          // (16,32,2)
    gemm_h<1,false><<<gsw, blk, SMEM_GEMM>>>(64,
        hh, EMB, 0, wh + 5 * NW, EMB, EMB, nullptr, wuh, EMB, nullptr, nullptr, 1.0f, 1.0f,
        (long long)PLANE);

    final_k<<<MTOT, 256>>>(xa, wvh, uvh, swb, mrg, out);   // swiglu + rmsnorm + residual
}

// round 13
// speedup vs baseline: 1.0488x; 1.0488x over previous
#include <cuda_runtime.h>
#include <cuda_fp16.h>
#include <mma.h>
#include <cstdint>

using namespace nvcuda;

#define SEQ 2048
#define EMB 2048
#define NB  2
#define NH  16
#define DH  128
#define MTOT (NB*SEQ)   // 4096
#define PLANE ((size_t)MTOT*EMB)

// ---------------- scratch (static device globals) ----------------
__device__ __half g_xh  [MTOT*EMB];
__device__ __half g_wh  [7][EMB*EMB];       // wq,wk,wv,wo,w0,sww,swv (contiguous)
__device__ __half g_qkvh[2][MTOT*EMB];      // plane0: qh [bh,t,d]; 1: kh [bh,s,d]
__device__ __half g_vp  [MTOT*EMB];         // [bh, d, s] (written by QKV epilogue)
__device__ float  g_ctx [MTOT*EMB];         // attention output (normalized fp32)
__device__ __half g_cth [MTOT*EMB];
__device__ float  g_xa  [MTOT*EMB];
__device__ __half g_x2h [MTOT*EMB];
__device__ __half g_hh  [MTOT*EMB];
__device__ __half g_wuh [2][MTOT*EMB];      // plane0: w, plane1: u (fp16)

__device__ __forceinline__ uint32_t smem_u32(const void* p) {
    uint32_t a;
    asm("{ .reg .u64 t; cvta.to.shared.u64 t, %1; cvt.u32.u64 %0, t; }" : "=r"(a) : "l"(p));
    return a;
}
__device__ __forceinline__ void ldsm4(uint32_t& r0, uint32_t& r1, uint32_t& r2, uint32_t& r3,
                                      uint32_t addr) {
    asm volatile("ldmatrix.sync.aligned.m8n8.x4.shared.b16 {%0,%1,%2,%3}, [%4];"
                 : "=r"(r0), "=r"(r1), "=r"(r2), "=r"(r3) : "r"(addr));
}
__device__ __forceinline__ void mma16816(float* c, uint32_t a0, uint32_t a1, uint32_t a2,
                                         uint32_t a3, uint32_t b0, uint32_t b1) {
    asm volatile("mma.sync.aligned.m16n8k16.row.col.f32.f16.f16.f32 "
                 "{%0,%1,%2,%3}, {%4,%5,%6,%7}, {%8,%9}, {%0,%1,%2,%3};"
                 : "+f"(c[0]), "+f"(c[1]), "+f"(c[2]), "+f"(c[3])
                 : "r"(a0), "r"(a1), "r"(a2), "r"(a3), "r"(b0), "r"(b1));
}

// ---------------- fp16 wmma NT GEMM, 3-stage cp.async ----------------
constexpr int BM = 128, BN = 128, PITCH = 40;          // pitch in halves
constexpr int STG_BYTES   = BM * PITCH * 2;            // 10240 per operand
constexpr int STAGE_BYTES = 2 * STG_BYTES;             // 20480 (A+B)
constexpr int NSTG = 3;
constexpr int SMEM_GEMM   = NSTG * STAGE_BYTES;        // 61440

// OMODE: 0 = fp32 out (opt RES); 1 = half plain out; 2 = QKV combined
//   (z=0 q head-split, z=1 k head-split scaled, z=2 v transposed into Vp)
template<int OMODE, bool RES>
__global__ void __launch_bounds__(256, 2)
gemm_h(int nk,
       const __half* __restrict__ A, int lda, int zRowA,
       const __half* __restrict__ B, int ldb, int zRowB,
       float* __restrict__ C, __half* __restrict__ Ch, int ldc,
       __half* __restrict__ Vp,
       const float* __restrict__ Rres, float alphaA, float alphaB,
       long long sC)
{
    const int bn0 = blockIdx.x * BN;
    const int bm0 = blockIdx.y * BM;
    const int z = blockIdx.z;

    extern __shared__ __align__(128) char smem[];
    const int tid  = threadIdx.x;
    const int wid  = tid >> 5;
    const int lane = tid & 31;
    const int wm = (wid & 3) * 32;
    const int wn = (wid >> 2) * 64;

    const __half* Abase = A + (size_t)(z * zRowA + bm0) * lda;
    const __half* Bbase = B + (size_t)(z * zRowB + bn0) * ldb;
    const long long coff = (long long)z * sC;

    auto load_chunk = [&](int kc) {
        const int st = kc % NSTG;
        char* sA = smem + st * STAGE_BYTES;
        char* sB = sA + STG_BYTES;
        const __half* ag = Abase + kc * 32;
        const __half* bg = Bbase + kc * 32;
        #pragma unroll
        for (int i = 0; i < 2; i++) {            // 512 16B segs per operand
            int idx = i * 256 + tid;
            int row = idx >> 2, seg = idx & 3;
            uint32_t da = smem_u32(sA + row * (PITCH * 2) + seg * 16);
            const __half* srca = ag + (size_t)row * lda + seg * 8;
            asm volatile("cp.async.cg.shared.global [%0], [%1], 16;" :: "r"(da), "l"(srca));
            uint32_t db = smem_u32(sB + row * (PITCH * 2) + seg * 16);
            const __half* srcb = bg + (size_t)row * ldb + seg * 8;
            asm volatile("cp.async.cg.shared.global [%0], [%1], 16;" :: "r"(db), "l"(srcb));
        }
        asm volatile("cp.async.commit_group;" ::: "memory");
    };

    wmma::fragment<wmma::accumulator, 16, 16, 16, float> acc[2][4];
    #pragma unroll
    for (int mi = 0; mi < 2; mi++)
        #pragma unroll
        for (int ni = 0; ni < 4; ni++) {
            if (RES)
                wmma::load_matrix_sync(acc[mi][ni],
                    Rres + coff + (long long)(bm0 + wm + mi * 16) * ldc + (bn0 + wn + ni * 16),
                    ldc, wmma::mem_row_major);
            else
                wmma::fill_fragment(acc[mi][ni], 0.0f);
        }

    load_chunk(0);
    if (nk > 1) load_chunk(1);

    for (int kc = 0; kc < nk; kc++) {
        if (kc + 1 < nk)
            asm volatile("cp.async.wait_group 1;" ::: "memory");
        else
            asm volatile("cp.async.wait_group 0;" ::: "memory");
        __syncthreads();                          // single sync per chunk
        if (kc + 2 < nk) load_chunk(kc + 2);

        const __half* sA = (const __half*)(smem + (kc % NSTG) * STAGE_BYTES);
        const __half* sB = sA + BM * PITCH;
        #pragma unroll
        for (int kk = 0; kk < 2; kk++) {
            wmma::fragment<wmma::matrix_a, 16, 16, 16, __half, wmma::row_major> af[2];
            #pragma unroll
            for (int mi = 0; mi < 2; mi++)
                wmma::load_matrix_sync(af[mi], sA + (wm + mi * 16) * PITCH + kk * 16, PITCH);
            #pragma unroll
            for (int nh = 0; nh < 2; nh++) {
                wmma::fragment<wmma::matrix_b, 16, 16, 16, __half, wmma::col_major> bf[2];
                #pragma unroll
                for (int j = 0; j < 2; j++)
                    wmma::load_matrix_sync(bf[j], sB + (wn + (nh * 2 + j) * 16) * PITCH + kk * 16, PITCH);
                #pragma unroll
                for (int mi = 0; mi < 2; mi++)
                    #pragma unroll
                    for (int j = 0; j < 2; j++)
                        wmma::mma_sync(acc[mi][nh * 2 + j], af[mi], bf[j], acc[mi][nh * 2 + j]);
            }
        }
    }

    const float alpha = (OMODE == 2) ? ((z == 1) ? alphaB : alphaA) : alphaA;
    if (alpha != 1.0f) {
        #pragma unroll
        for (int mi = 0; mi < 2; mi++)
            #pragma unroll
            for (int ni = 0; ni < 4; ni++)
                #pragma unroll
                for (int e = 0; e < acc[mi][ni].num_elements; e++)
                    acc[mi][ni].x[e] *= alpha;
    }

    if (OMODE == 0) {
        float* Cp = C + coff;
        #pragma unroll
        for (int mi = 0; mi < 2; mi++)
            #pragma unroll
            for (int ni = 0; ni < 4; ni++)
                wmma::store_matrix_sync(
                    Cp + (long long)(bm0 + wm + mi * 16) * ldc + (bn0 + wn + ni * 16),
                    acc[mi][ni], ldc, wmma::mem_row_major);
    } else {
        __syncthreads();                          // all MMAs done before smem reuse
        float* stg = (float*)smem + wid * 320;    // 16x16 tile, pitch 20
        __half* Cp = (OMODE == 2) ? (Ch + (size_t)z * PLANE) : Ch;
        const bool vmode = (OMODE == 2) && (z == 2);
        #pragma unroll
        for (int mi = 0; mi < 2; mi++)
            #pragma unroll
            for (int ni = 0; ni < 4; ni++) {
                wmma::store_matrix_sync(stg, acc[mi][ni], 20, wmma::mem_row_major);
                __syncwarp();
                if (vmode) {
                    // tile = 16 tokens x 16 heads at fixed d; transpose to vp[bh][d][s]
                    const int c  = lane >> 1;      // head within tile
                    const int hf = lane & 1;       // token half (8 each)
                    __half hv8[8];
                    #pragma unroll
                    for (int rr = 0; rr < 8; rr++)
                        hv8[rr] = __float2half_rn(stg[(hf * 8 + rr) * 20 + c]);
                    const int grow0 = bm0 + wm + mi * 16;
                    const int bb = grow0 >> 11, t0 = grow0 & 2047;
                    const int d = (bn0 + wn + ni * 16) >> 4;
                    __half* dstv = Vp + ((size_t)((bb << 4) + c) * DH + d) * SEQ + t0 + hf * 8;
                    *reinterpret_cast<uint4*>(dstv) = *reinterpret_cast<uint4*>(hv8);
                } else {
                    const int r  = lane >> 1;
                    const int cb = (lane & 1) * 8;
                    __half2 hv[4];
                    #pragma unroll
                    for (int j = 0; j < 4; j++)
                        hv[j] = __floats2half2_rn(stg[r * 20 + cb + 2 * j],
                                                  stg[r * 20 + cb + 2 * j + 1]);
                    const int grow = bm0 + wm + mi * 16 + r;
                    const int gcol = wn + ni * 16 + cb;
                    __half* dst;
                    if (OMODE == 2) {              // q/k head-split [bh, t, d]
                        const int b = grow >> 11, tt = grow & 2047;
                        dst = Cp + ((size_t)((b << 4) + (bn0 >> 7)) * SEQ + tt) * DH + gcol;
                    } else {
                        dst = Cp + coff + (size_t)grow * ldc + bn0 + gcol;
                    }
                    *reinterpret_cast<uint4*>(dst) = *reinterpret_cast<uint4*>(hv);
                }
                __syncwarp();
            }
    }
}

// ------ FA2-style fused attention: register softmax, mma.sync, dbl-buf K/V ----
// q-tile 128 (8 warps x 16 rows), k-tile 64. QK C-fragments are warp-private;
// exp/mask/rowsum in registers; P fragments feed PV directly (layout identity).
constexpr int AQP = 136;                       // Q/K pitch (halves)
constexpr int AVP = 72;                        // V pitch (halves)
constexpr int KSTG = 64 * AQP * 2;             // 17408
constexpr int VSTG = 128 * AVP * 2;            // 18432
constexpr int OFF_K = 128 * AQP * 2;           // 34816 (after Q)
constexpr int OFF_V = OFF_K + 2 * KSTG;        // 69632
constexpr int SMEM_ATT = OFF_V + 2 * VSTG;     // 106496

__global__ void __launch_bounds__(256, 2)
attn_reg128(const __half* __restrict__ qh,   // [bh, t, d]
            const __half* __restrict__ kh,   // [bh, s, d] (pre-scaled)
            const __half* __restrict__ vp,   // [bh, d, s]
            float* __restrict__ ctx)         // [b, t, E] normalized fp32
{
    extern __shared__ __align__(128) char smem[];
    __half* Qs = (__half*)smem;

    const int bh = blockIdx.x & 31;
    const int qt = 15 - (blockIdx.x >> 5);     // heavy q-tiles first
    const int b = bh >> 4, h = bh & 15;
    const int tid  = threadIdx.x;
    const int wid  = tid >> 5;
    const int lane = tid & 31;
    const int nkt = 2 * qt + 2;

    auto load_kv = [&](int kt, int st) {       // K 64x128 + V 128x64 into stage st
        const __half* kg = kh + ((size_t)bh * SEQ + kt * 64) * DH;
        const __half* vg = vp + (size_t)bh * DH * SEQ + kt * 64;
        char* Kst = smem + OFF_K + st * KSTG;
        char* Vst = smem + OFF_V + st * VSTG;
        #pragma unroll
        for (int i = 0; i < 4; i++) {
            int s = i * 256 + tid;
            int rk = s >> 4, ck = s & 15;
            uint32_t dk = smem_u32(Kst + (rk * AQP + ck * 8) * 2);
            asm volatile("cp.async.cg.shared.global [%0], [%1], 16;"
                         :: "r"(dk), "l"(kg + (size_t)rk * DH + ck * 8));
            int rv = s >> 3, cv = s & 7;
            uint32_t dv = smem_u32(Vst + (rv * AVP + cv * 8) * 2);
            asm volatile("cp.async.cg.shared.global [%0], [%1], 16;"
                         :: "r"(dv), "l"(vg + (size_t)rv * SEQ + cv * 8));
        }
    };

    // prologue group 1: Q + KV(0) stage 0
    {
        const __half* qg = qh + ((size_t)bh * SEQ + qt * 128) * DH;
        #pragma unroll
        for (int i = 0; i < 8; i++) {
            int s = i * 256 + tid;
            int row = s >> 4, seg = s & 15;
            uint32_t dst = smem_u32(Qs + row * AQP + seg * 8);
            asm volatile("cp.async.cg.shared.global [%0], [%1], 16;"
                         :: "r"(dst), "l"(qg + (size_t)row * DH + seg * 8));
        }
        load_kv(0, 0);
        asm volatile("cp.async.commit_group;" ::: "memory");
    }
    // prologue group 2: KV(1) stage 1
    if (nkt > 1) load_kv(1, 1);
    asm volatile("cp.async.commit_group;" ::: "memory");

    float oacc[16][4];
    #pragma unroll
    for (int n = 0; n < 16; n++)
        #pragma unroll
        for (int e = 0; e < 4; e++) oacc[n][e] = 0.0f;
    float rsum0 = 0.0f, rsum1 = 0.0f;

    // ldmatrix source addresses (per-thread row pointers)
    const uint32_t qbase = smem_u32(Qs + (wid * 16 + (lane & 15)) * AQP + (lane >> 4) * 8);
    const int frow = ((lane >> 4) << 3) + (lane & 7);      // fragment row
    const int fcol = ((lane >> 3) & 1) * 8;                // fragment col offset
    const int r0g = qt * 128 + wid * 16 + (lane >> 2);     // global q row (c0,c1)
    const int ce  = (lane & 3) * 2;                        // col-in-tile even index

    for (int kt = 0; kt < nkt; kt++) {
        asm volatile("cp.async.wait_group 1;" ::: "memory");   // KV(kt) landed
        __syncthreads();
        const int st = kt & 1;
        const uint32_t kbase = smem_u32(smem + OFF_K + st * KSTG) + (uint32_t)(frow * AQP + fcol) * 2;
        const uint32_t vbase = smem_u32(smem + OFF_V + st * VSTG) + (uint32_t)(frow * AVP + fcol) * 2;

        // ---- S = Q @ K^T : 8 private 16x8 accumulators ----
        float sacc[8][4];
        #pragma unroll
        for (int n = 0; n < 8; n++)
            #pragma unroll
            for (int e = 0; e < 4; e++) sacc[n][e] = 0.0f;
        #pragma unroll
        for (int kk = 0; kk < 8; kk++) {
            uint32_t a0, a1, a2, a3;
            ldsm4(a0, a1, a2, a3, qbase + (uint32_t)(kk * 16) * 2);
            #pragma unroll
            for (int np = 0; np < 4; np++) {
                uint32_t b0, b1, b2, b3;
                ldsm4(b0, b1, b2, b3, kbase + (uint32_t)(np * 16 * AQP + kk * 16) * 2);
                mma16816(sacc[2 * np],     a0, a1, a2, a3, b0, b1);
                mma16816(sacc[2 * np + 1], a0, a1, a2, a3, b2, b3);
            }
        }

        // ---- exp + causal mask + rowsum, build P fragments (registers only) ----
        uint32_t pa[16];
        #pragma unroll
        for (int n = 0; n < 8; n++) {
            const int colb = kt * 64 + n * 8 + ce;
            float s0 = (colb     <= r0g)     ? __expf(sacc[n][0]) : 0.0f;
            float s1 = (colb + 1 <= r0g)     ? __expf(sacc[n][1]) : 0.0f;
            float s2 = (colb     <= r0g + 8) ? __expf(sacc[n][2]) : 0.0f;
            float s3 = (colb + 1 <= r0g + 8) ? __expf(sacc[n][3]) : 0.0f;
            rsum0 += s0 + s1;
            rsum1 += s2 + s3;
            __half2 h01 = __floats2half2_rn(s0, s1);
            __half2 h23 = __floats2half2_rn(s2, s3);
            pa[n * 2]     = *reinterpret_cast<uint32_t*>(&h01);
            pa[n * 2 + 1] = *reinterpret_cast<uint32_t*>(&h23);
        }

        // ---- O += P @ V^T (A = P fragments, layout identity) ----
        #pragma unroll
        for (int j = 0; j < 4; j++) {
            const uint32_t a0 = pa[4 * j], a1 = pa[4 * j + 1];
            const uint32_t a2 = pa[4 * j + 2], a3 = pa[4 * j + 3];
            #pragma unroll
            for (int dp = 0; dp < 8; dp++) {
                uint32_t b0, b1, b2, b3;
                ldsm4(b0, b1, b2, b3, vbase + (uint32_t)(dp * 16 * AVP + j * 16) * 2);
                mma16816(oacc[2 * dp],     a0, a1, a2, a3, b0, b1);
                mma16816(oacc[2 * dp + 1], a0, a1, a2, a3, b2, b3);
            }
        }
        __syncthreads();                          // all warps done with stage st
        if (kt + 2 < nkt) load_kv(kt + 2, st);    // prefetch into freed stage
        asm volatile("cp.async.commit_group;" ::: "memory");
    }

    // ---- normalize and write ctx[b, t, h*DH + d] ----
    rsum0 += __shfl_xor_sync(0xffffffffu, rsum0, 1);
    rsum0 += __shfl_xor_sync(0xffffffffu, rsum0, 2);
    rsum1 += __shfl_xor_sync(0xffffffffu, rsum1, 1);
    rsum1 += __shfl_xor_sync(0xffffffffu, rsum1, 2);
    const float inv0 = 1.0f / rsum0;
    const float inv1 = 1.0f / rsum1;
    float* base0 = ctx + ((size_t)(b * SEQ + r0g)) * EMB + h * DH + ce;
    float* base1 = base0 + (size_t)8 * EMB;
    #pragma unroll
    for (int dn = 0; dn < 16; dn++) {
        float2 v0 = make_float2(oacc[dn][0] * inv0, oacc[dn][1] * inv0);
        float2 v1 = make_float2(oacc[dn][2] * inv1, oacc[dn][3] * inv1);
        *reinterpret_cast<float2*>(base0 + dn * 8) = v0;
        *reinterpret_cast<float2*>(base1 + dn * 8) = v1;
    }
}

// ---------------- block reductions ----------------
__device__ __forceinline__ float blk_sum(float v) {
    __shared__ float sh_s[32];
    __shared__ float tot_s;
    int lane = threadIdx.x & 31, w = threadIdx.x >> 5;
    #pragma unroll
    for (int o = 16; o; o >>= 1) v += __shfl_xor_sync(0xffffffffu, v, o);
    if (lane == 0) sh_s[w] = v;
    __syncthreads();
    if (threadIdx.x == 0) {
        float r = 0.f; int nw = blockDim.x >> 5;
        for (int i = 0; i < nw; i++) r += sh_s[i];
        tot_s = r;
    }
    __syncthreads();
    float r = tot_s;
    __syncthreads();
    return r;
}

// ---------------- conversions / norms ----------------
__global__ void f2h_k(const float* __restrict__ in, __half* __restrict__ out) {
    int i = (blockIdx.x * blockDim.x + threadIdx.x) * 4;
    float4 v = *reinterpret_cast<const float4*>(in + i);
    __half2 h[2];
    h[0] = __floats2half2_rn(v.x, v.y);
    h[1] = __floats2half2_rn(v.z, v.w);
    *reinterpret_cast<uint2*>(out + i) = *reinterpret_cast<uint2*>(h);
}

struct W7 { const float* p[7]; };
__global__ void f2h7_k(W7 ws, __half* __restrict__ out) {
    const int plane = blockIdx.y;
    const float* in = ws.p[plane];
    __half* o = out + (size_t)plane * EMB * EMB;
    int i = (blockIdx.x * blockDim.x + threadIdx.x) * 4;
    float4 v = *reinterpret_cast<const float4*>(in + i);
    __half2 h[2];
    h[0] = __floats2half2_rn(v.x, v.y);
    h[1] = __floats2half2_rn(v.z, v.w);
    *reinterpret_cast<uint2*>(o + i) = *reinterpret_cast<uint2*>(h);
}

__global__ void layernorm_h(const float* __restrict__ in, __half* __restrict__ out,
                            const float* __restrict__ g, const float* __restrict__ b) {
    const float* row = in + (size_t)blockIdx.x * EMB;
    __half* orow = out + (size_t)blockIdx.x * EMB;
    __shared__ float buf[EMB];
    float s = 0.f;
    for (int i = threadIdx.x; i < EMB; i += blockDim.x) { float v = row[i]; buf[i] = v; s += v; }
    const float mu = blk_sum(s) * (1.0f / EMB);
    float sq = 0.f;
    for (int i = threadIdx.x; i < EMB; i += blockDim.x) { float d = buf[i] - mu; sq += d * d; }
    const float var = blk_sum(sq) * (1.0f / EMB);
    const float inv = rsqrtf(var + 1e-5f);
    for (int i = threadIdx.x; i < EMB; i += blockDim.x)
        orow[i] = __float2half_rn((buf[i] - mu) * inv * g[i] + b[i]);
}

// x := rmsnorm(x) (fp32, residual base) and xh := half(x)
__global__ void rmsnorm_dual(float* __restrict__ x, __half* __restrict__ xh,
                             const float* __restrict__ g) {
    float* row = x + (size_t)blockIdx.x * EMB;
    __half* orow = xh + (size_t)blockIdx.x * EMB;
    __shared__ float buf[EMB];
    float ss = 0.f;
    for (int i = threadIdx.x; i < EMB; i += blockDim.x) { float v = row[i]; buf[i] = v; ss += v * v; }
    ss = blk_sum(ss);
    const float sc = rsqrtf(ss * (1.0f / EMB) + 1e-6f);
    for (int i = threadIdx.x; i < EMB; i += blockDim.x) {
        float r = g[i] * buf[i] * sc;
        row[i] = r;
        orow[i] = __float2half_rn(r);
    }
}

// out = x2 + mlp_rms_g * g * rsqrt(mean(g^2)+eps),  g = w*sigmoid(beta*w)*u  (half w,u)
__global__ void final_k(const float* __restrict__ x2, const __half* __restrict__ wv,
                        const __half* __restrict__ uv, const float* __restrict__ beta,
                        const float* __restrict__ gamma, float* __restrict__ out) {
    const size_t r = blockIdx.x;
    const float bet = beta[0];
    const __half* wrow = wv + r * EMB;
    const __half* urow = uv + r * EMB;
    __shared__ float buf[EMB];
    float ss = 0.f;
    for (int i = threadIdx.x; i < EMB; i += blockDim.x) {
        float wq = __half2float(wrow[i]);
        float s = 1.0f / (1.0f + __expf(-bet * wq));
        float gq = wq * s * __half2float(urow[i]);
        buf[i] = gq; ss += gq * gq;
    }
    ss = blk_sum(ss);
    const float sc = rsqrtf(ss * (1.0f / EMB) + 1e-6f);
    for (int i = threadIdx.x; i < EMB; i += blockDim.x)
        out[r * EMB + i] = x2[r * EMB + i] + gamma[i] * buf[i] * sc;
}

// ---------------- launcher ----------------
extern "C" void kernel_launch(void* const* d_in, const int* in_sizes, int n_in,
                              void* d_out, int out_size) {
    const float* x     = (const float*)d_in[0];
    const float* Wq    = (const float*)d_in[1];
    const float* Wk    = (const float*)d_in[2];
    const float* Wv    = (const float*)d_in[3];
    const float* Wo    = (const float*)d_in[4];
    const float* ln_g  = (const float*)d_in[5];
    const float* ln_b  = (const float*)d_in[6];
    const float* rms_g = (const float*)d_in[7];
    const float* W0    = (const float*)d_in[8];
    const float* swW   = (const float*)d_in[9];
    const float* swV   = (const float*)d_in[10];
    const float* swb   = (const float*)d_in[11];
    const float* mrg   = (const float*)d_in[12];
    float* out = (float*)d_out;

    __half *xh, *wh, *qkv, *vp, *cth, *x2h, *hh, *wuh;
    float *ctx, *xa;
    cudaGetSymbolAddress((void**)&xh,   g_xh);
    cudaGetSymbolAddress((void**)&wh,   g_wh);
    cudaGetSymbolAddress((void**)&qkv,  g_qkvh);
    cudaGetSymbolAddress((void**)&vp,   g_vp);
    cudaGetSymbolAddress((void**)&ctx,  g_ctx);
    cudaGetSymbolAddress((void**)&cth,  g_cth);
    cudaGetSymbolAddress((void**)&xa,   g_xa);
    cudaGetSymbolAddress((void**)&x2h,  g_x2h);
    cudaGetSymbolAddress((void**)&hh,   g_hh);
    cudaGetSymbolAddress((void**)&wuh,  g_wuh);

    __half* qh = qkv + 0 * PLANE;
    __half* kh = qkv + 1 * PLANE;
    __half* wvh = wuh + 0 * PLANE;
    __half* uvh = wuh + 1 * PLANE;
    const long long NW = (long long)EMB * EMB;

    cudaFuncSetAttribute(gemm_h<2,false>, cudaFuncAttributeMaxDynamicSharedMemorySize, SMEM_GEMM);
    cudaFuncSetAttribute(gemm_h<0,true >, cudaFuncAttributeMaxDynamicSharedMemorySize, SMEM_GEMM);
    cudaFuncSetAttribute(gemm_h<1,false>, cudaFuncAttributeMaxDynamicSharedMemorySize, SMEM_GEMM);
    cudaFuncSetAttribute(attn_reg128,     cudaFuncAttributeMaxDynamicSharedMemorySize, SMEM_ATT);

    const float scale = 0.08838834764831845f;  // 1/sqrt(128)
    const int NEW = MTOT * EMB;                // 8,388,608
    dim3 blk(256);

    // fp32 -> fp16 operand conversions
    f2h_k<<<NEW / 1024, 256>>>(x, xh);
    W7 ws; ws.p[0]=Wq; ws.p[1]=Wk; ws.p[2]=Wv; ws.p[3]=Wo; ws.p[4]=W0; ws.p[5]=swW; ws.p[6]=swV;
    f2h7_k<<<dim3(NW / 1024, 7), 256>>>(ws, wh);

    // merged QKV projection: z=0 q head-split, z=1 k scaled head-split,
    // z=2 v transposed straight into vp (repack fused)
    dim3 gqkv(EMB / BN, MTOT / BM, 3);         // (16,32,3)
    gemm_h<2,false><<<gqkv, blk, SMEM_GEMM>>>(64,
        xh, EMB, 0, wh, EMB, EMB, nullptr, qkv, EMB, vp, nullptr, 1.0f, scale, 0);

    // FA2-style fused attention (register softmax), normalized fp32 ctx
    attn_reg128<<<512, blk, SMEM_ATT>>>(qh, kh, vp, ctx);

    layernorm_h<<<MTOT, 256>>>(ctx, cth, ln_g, ln_b);

    // xa = x + cth @ Wo^T (fp32, residual fused via accumulator init)
    dim3 gp(EMB / BN, MTOT / BM, 1);           // (16,32,1)
    gemm_h<0,true><<<gp, blk, SMEM_GEMM>>>(64,
        cth, EMB, 0, wh + 3 * NW, EMB, 0, xa, nullptr, EMB, nullptr, x, 1.0f, 1.0f, 0);

    rmsnorm_dual<<<MTOT, 256>>>(xa, x2h, rms_g);

    // h = x2 @ W0^T (half out)
    gemm_h<1,false><<<gp, blk, SMEM_GEMM>>>(64,
        x2h, EMB, 0, wh + 4 * NW, EMB, 0, nullptr, hh, EMB, nullptr, nullptr, 1.0f, 1.0f, 0);

    // merged swW/swV: z selects weight plane + half output plane
    dim3 gsw(EMB / BN, MTOT / BM, 2);          // (16,32,2)
    gemm_h<1,false><<<gsw, blk, SMEM_GEMM>>>(64,
        hh, EMB, 0, wh + 5 * NW, EMB, EMB, nullptr, wuh, EMB, nullptr, nullptr, 1.0f, 1.0f,
        (long long)PLANE);

    final_k<<<MTOT, 256>>>(xa, wvh, uvh, swb, mrg, out);   // swiglu + rmsnorm + residual
}

// round 14
// speedup vs baseline: 1.1488x; 1.0954x over previous
#include <cuda_runtime.h>
#include <cuda_fp16.h>
#include <mma.h>
#include <cstdint>

using namespace nvcuda;

#define SEQ 2048
#define EMB 2048
#define NB  2
#define NH  16
#define DH  128
#define MTOT (NB*SEQ)   // 4096
#define PLANE ((size_t)MTOT*EMB)

// ---------------- scratch (static device globals) ----------------
__device__ __half g_xh  [MTOT*EMB];
__device__ __half g_wh  [7][EMB*EMB];       // wq,wk,wv,wo,w0,sww,swv (contiguous)
__device__ __half g_qkvh[2][MTOT*EMB];      // plane0: qh [bh,t,d]; 1: kh [bh,s,d]
__device__ __half g_vp  [MTOT*EMB];         // [bh, d, s] (written by QKV epilogue)
__device__ float  g_ctx [MTOT*EMB];         // attention output (normalized fp32)
__device__ __half g_cth [MTOT*EMB];
__device__ float  g_xa  [MTOT*EMB];
__device__ __half g_x2h [MTOT*EMB];
__device__ __half g_hh  [MTOT*EMB];
__device__ __half g_wuh [2][MTOT*EMB];      // plane0: w, plane1: u (fp16)

__device__ __forceinline__ uint32_t smem_u32(const void* p) {
    uint32_t a;
    asm("{ .reg .u64 t; cvta.to.shared.u64 t, %1; cvt.u32.u64 %0, t; }" : "=r"(a) : "l"(p));
    return a;
}
__device__ __forceinline__ void ldsm4(uint32_t& r0, uint32_t& r1, uint32_t& r2, uint32_t& r3,
                                      uint32_t addr) {
    asm volatile("ldmatrix.sync.aligned.m8n8.x4.shared.b16 {%0,%1,%2,%3}, [%4];"
                 : "=r"(r0), "=r"(r1), "=r"(r2), "=r"(r3) : "r"(addr));
}
__device__ __forceinline__ void mma16816(float* c, uint32_t a0, uint32_t a1, uint32_t a2,
                                         uint32_t a3, uint32_t b0, uint32_t b1) {
    asm volatile("mma.sync.aligned.m16n8k16.row.col.f32.f16.f16.f32 "
                 "{%0,%1,%2,%3}, {%4,%5,%6,%7}, {%8,%9}, {%0,%1,%2,%3};"
                 : "+f"(c[0]), "+f"(c[1]), "+f"(c[2]), "+f"(c[3])
                 : "r"(a0), "r"(a1), "r"(a2), "r"(a3), "r"(b0), "r"(b1));
}

// ---------------- fp16 wmma NT GEMM, 3-stage cp.async ----------------
// Fragment loads double-buffered across the two kk halves so LDSM(kk=1)
// overlaps MMA(kk=0) — breaks the all-warps-lockstep LDSM/HMMA alternation.
constexpr int BM = 128, BN = 128, PITCH = 40;          // pitch in halves
constexpr int STG_BYTES   = BM * PITCH * 2;            // 10240 per operand
constexpr int STAGE_BYTES = 2 * STG_BYTES;             // 20480 (A+B)
constexpr int NSTG = 3;
constexpr int SMEM_GEMM   = NSTG * STAGE_BYTES;        // 61440

// OMODE: 0 = fp32 out (opt RES); 1 = half plain out; 2 = QKV combined
//   (z=0 q head-split, z=1 k head-split scaled, z=2 v transposed into Vp)
template<int OMODE, bool RES>
__global__ void __launch_bounds__(256, 2)
gemm_h(int nk,
       const __half* __restrict__ A, int lda, int zRowA,
       const __half* __restrict__ B, int ldb, int zRowB,
       float* __restrict__ C, __half* __restrict__ Ch, int ldc,
       __half* __restrict__ Vp,
       const float* __restrict__ Rres, float alphaA, float alphaB,
       long long sC)
{
    const int bn0 = blockIdx.x * BN;
    const int bm0 = blockIdx.y * BM;
    const int z = blockIdx.z;

    extern __shared__ __align__(128) char smem[];
    const int tid  = threadIdx.x;
    const int wid  = tid >> 5;
    const int lane = tid & 31;
    const int wm = (wid & 3) * 32;
    const int wn = (wid >> 2) * 64;

    const __half* Abase = A + (size_t)(z * zRowA + bm0) * lda;
    const __half* Bbase = B + (size_t)(z * zRowB + bn0) * ldb;
    const long long coff = (long long)z * sC;

    auto load_chunk = [&](int kc) {
        const int st = kc % NSTG;
        char* sA = smem + st * STAGE_BYTES;
        char* sB = sA + STG_BYTES;
        const __half* ag = Abase + kc * 32;
        const __half* bg = Bbase + kc * 32;
        #pragma unroll
        for (int i = 0; i < 2; i++) {            // 512 16B segs per operand
            int idx = i * 256 + tid;
            int row = idx >> 2, seg = idx & 3;
            uint32_t da = smem_u32(sA + row * (PITCH * 2) + seg * 16);
            const __half* srca = ag + (size_t)row * lda + seg * 8;
            asm volatile("cp.async.cg.shared.global [%0], [%1], 16;" :: "r"(da), "l"(srca));
            uint32_t db = smem_u32(sB + row * (PITCH * 2) + seg * 16);
            const __half* srcb = bg + (size_t)row * ldb + seg * 8;
            asm volatile("cp.async.cg.shared.global [%0], [%1], 16;" :: "r"(db), "l"(srcb));
        }
        asm volatile("cp.async.commit_group;" ::: "memory");
    };

    wmma::fragment<wmma::accumulator, 16, 16, 16, float> acc[2][4];
    #pragma unroll
    for (int mi = 0; mi < 2; mi++)
        #pragma unroll
        for (int ni = 0; ni < 4; ni++) {
            if (RES)
                wmma::load_matrix_sync(acc[mi][ni],
                    Rres + coff + (long long)(bm0 + wm + mi * 16) * ldc + (bn0 + wn + ni * 16),
                    ldc, wmma::mem_row_major);
            else
                wmma::fill_fragment(acc[mi][ni], 0.0f);
        }

    load_chunk(0);
    if (nk > 1) load_chunk(1);

    for (int kc = 0; kc < nk; kc++) {
        if (kc + 1 < nk)
            asm volatile("cp.async.wait_group 1;" ::: "memory");
        else
            asm volatile("cp.async.wait_group 0;" ::: "memory");
        __syncthreads();                          // single sync per chunk

        const __half* sA = (const __half*)(smem + (kc % NSTG) * STAGE_BYTES);
        const __half* sB = sA + BM * PITCH;

        // double-buffered fragment registers: [buf][...]
        wmma::fragment<wmma::matrix_a, 16, 16, 16, __half, wmma::row_major> af[2][2];
        wmma::fragment<wmma::matrix_b, 16, 16, 16, __half, wmma::col_major> bf[2][4];

        // LDSM kk=0 into buf 0
        #pragma unroll
        for (int mi = 0; mi < 2; mi++)
            wmma::load_matrix_sync(af[0][mi], sA + (wm + mi * 16) * PITCH, PITCH);
        #pragma unroll
        for (int j = 0; j < 4; j++)
            wmma::load_matrix_sync(bf[0][j], sB + (wn + j * 16) * PITCH, PITCH);

        if (kc + 2 < nk) load_chunk(kc + 2);      // gmem prefetch under LDSM latency

        // LDSM kk=1 into buf 1 (overlaps MMA(kk=0) below)
        #pragma unroll
        for (int mi = 0; mi < 2; mi++)
            wmma::load_matrix_sync(af[1][mi], sA + (wm + mi * 16) * PITCH + 16, PITCH);
        #pragma unroll
        for (int j = 0; j < 4; j++)
            wmma::load_matrix_sync(bf[1][j], sB + (wn + j * 16) * PITCH + 16, PITCH);

        #pragma unroll
        for (int mi = 0; mi < 2; mi++)
            #pragma unroll
            for (int j = 0; j < 4; j++)
                wmma::mma_sync(acc[mi][j], af[0][mi], bf[0][j], acc[mi][j]);
        #pragma unroll
        for (int mi = 0; mi < 2; mi++)
            #pragma unroll
            for (int j = 0; j < 4; j++)
                wmma::mma_sync(acc[mi][j], af[1][mi], bf[1][j], acc[mi][j]);
    }

    const float alpha = (OMODE == 2) ? ((z == 1) ? alphaB : alphaA) : alphaA;
    if (alpha != 1.0f) {
        #pragma unroll
        for (int mi = 0; mi < 2; mi++)
            #pragma unroll
            for (int ni = 0; ni < 4; ni++)
                #pragma unroll
                for (int e = 0; e < acc[mi][ni].num_elements; e++)
                    acc[mi][ni].x[e] *= alpha;
    }

    if (OMODE == 0) {
        float* Cp = C + coff;
        #pragma unroll
        for (int mi = 0; mi < 2; mi++)
            #pragma unroll
            for (int ni = 0; ni < 4; ni++)
                wmma::store_matrix_sync(
                    Cp + (long long)(bm0 + wm + mi * 16) * ldc + (bn0 + wn + ni * 16),
                    acc[mi][ni], ldc, wmma::mem_row_major);
    } else {
        __syncthreads();                          // all MMAs done before smem reuse
        float* stg = (float*)smem + wid * 320;    // 16x16 tile, pitch 20
        __half* Cp = (OMODE == 2) ? (Ch + (size_t)z * PLANE) : Ch;
        const bool vmode = (OMODE == 2) && (z == 2);
        #pragma unroll
        for (int mi = 0; mi < 2; mi++)
            #pragma unroll
            for (int ni = 0; ni < 4; ni++) {
                wmma::store_matrix_sync(stg, acc[mi][ni], 20, wmma::mem_row_major);
                __syncwarp();
                if (vmode) {
                    // tile = 16 tokens x 16 heads at fixed d; transpose to vp[bh][d][s]
                    const int c  = lane >> 1;      // head within tile
                    const int hf = lane & 1;       // token half (8 each)
                    __half hv8[8];
                    #pragma unroll
                    for (int rr = 0; rr < 8; rr++)
                        hv8[rr] = __float2half_rn(stg[(hf * 8 + rr) * 20 + c]);
                    const int grow0 = bm0 + wm + mi * 16;
                    const int bb = grow0 >> 11, t0 = grow0 & 2047;
                    const int d = (bn0 + wn + ni * 16) >> 4;
                    __half* dstv = Vp + ((size_t)((bb << 4) + c) * DH + d) * SEQ + t0 + hf * 8;
                    *reinterpret_cast<uint4*>(dstv) = *reinterpret_cast<uint4*>(hv8);
                } else {
                    const int r  = lane >> 1;
                    const int cb = (lane & 1) * 8;
                    __half2 hv[4];
                    #pragma unroll
                    for (int j = 0; j < 4; j++)
                        hv[j] = __floats2half2_rn(stg[r * 20 + cb + 2 * j],
                                                  stg[r * 20 + cb + 2 * j + 1]);
                    const int grow = bm0 + wm + mi * 16 + r;
                    const int gcol = wn + ni * 16 + cb;
                    __half* dst;
                    if (OMODE == 2) {              // q/k head-split [bh, t, d]
                        const int b = grow >> 11, tt = grow & 2047;
                        dst = Cp + ((size_t)((b << 4) + (bn0 >> 7)) * SEQ + tt) * DH + gcol;
                    } else {
                        dst = Cp + coff + (size_t)grow * ldc + bn0 + gcol;
                    }
                    *reinterpret_cast<uint4*>(dst) = *reinterpret_cast<uint4*>(hv);
                }
                __syncwarp();
            }
    }
}

// ------ FA2-style fused attention: register softmax, mma.sync, dbl-buf K/V ----
constexpr int AQP = 136;                       // Q/K pitch (halves)
constexpr int AVP = 72;                        // V pitch (halves)
constexpr int KSTG = 64 * AQP * 2;             // 17408
constexpr int VSTG = 128 * AVP * 2;            // 18432
constexpr int OFF_K = 128 * AQP * 2;           // 34816 (after Q)
constexpr int OFF_V = OFF_K + 2 * KSTG;        // 69632
constexpr int SMEM_ATT = OFF_V + 2 * VSTG;     // 106496

__global__ void __launch_bounds__(256, 2)
attn_reg128(const __half* __restrict__ qh,   // [bh, t, d]
            const __half* __restrict__ kh,   // [bh, s, d] (pre-scaled)
            const __half* __restrict__ vp,   // [bh, d, s]
            float* __restrict__ ctx)         // [b, t, E] normalized fp32
{
    extern __shared__ __align__(128) char smem[];
    __half* Qs = (__half*)smem;

    const int bh = blockIdx.x & 31;
    const int qt = 15 - (blockIdx.x >> 5);     // heavy q-tiles first
    const int b = bh >> 4, h = bh & 15;
    const int tid  = threadIdx.x;
    const int wid  = tid >> 5;
    const int lane = tid & 31;
    const int nkt = 2 * qt + 2;

    auto load_kv = [&](int kt, int st) {       // K 64x128 + V 128x64 into stage st
        const __half* kg = kh + ((size_t)bh * SEQ + kt * 64) * DH;
        const __half* vg = vp + (size_t)bh * DH * SEQ + kt * 64;
        char* Kst = smem + OFF_K + st * KSTG;
        char* Vst = smem + OFF_V + st * VSTG;
        #pragma unroll
        for (int i = 0; i < 4; i++) {
            int s = i * 256 + tid;
            int rk = s >> 4, ck = s & 15;
            uint32_t dk = smem_u32(Kst + (rk * AQP + ck * 8) * 2);
            asm volatile("cp.async.cg.shared.global [%0], [%1], 16;"
                         :: "r"(dk), "l"(kg + (size_t)rk * DH + ck * 8));
            int rv = s >> 3, cv = s & 7;
            uint32_t dv = smem_u32(Vst + (rv * AVP + cv * 8) * 2);
            asm volatile("cp.async.cg.shared.global [%0], [%1], 16;"
                         :: "r"(dv), "l"(vg + (size_t)rv * SEQ + cv * 8));
        }
    };

    // prologue group 1: Q + KV(0) stage 0
    {
        const __half* qg = qh + ((size_t)bh * SEQ + qt * 128) * DH;
        #pragma unroll
        for (int i = 0; i < 8; i++) {
            int s = i * 256 + tid;
            int row = s >> 4, seg = s & 15;
            uint32_t dst = smem_u32(Qs + row * AQP + seg * 8);
            asm volatile("cp.async.cg.shared.global [%0], [%1], 16;"
                         :: "r"(dst), "l"(qg + (size_t)row * DH + seg * 8));
        }
        load_kv(0, 0);
        asm volatile("cp.async.commit_group;" ::: "memory");
    }
    // prologue group 2: KV(1) stage 1
    if (nkt > 1) load_kv(1, 1);
    asm volatile("cp.async.commit_group;" ::: "memory");

    float oacc[16][4];
    #pragma unroll
    for (int n = 0; n < 16; n++)
        #pragma unroll
        for (int e = 0; e < 4; e++) oacc[n][e] = 0.0f;
    float rsum0 = 0.0f, rsum1 = 0.0f;

    const uint32_t qbase = smem_u32(Qs + (wid * 16 + (lane & 15)) * AQP + (lane >> 4) * 8);
    const int frow = ((lane >> 4) << 3) + (lane & 7);      // fragment row
    const int fcol = ((lane >> 3) & 1) * 8;                // fragment col offset
    const int r0g = qt * 128 + wid * 16 + (lane >> 2);     // global q row (c0,c1)
    const int ce  = (lane & 3) * 2;                        // col-in-tile even index

    for (int kt = 0; kt < nkt; kt++) {
        asm volatile("cp.async.wait_group 1;" ::: "memory");   // KV(kt) landed
        __syncthreads();
        const int st = kt & 1;
        const uint32_t kbase = smem_u32(smem + OFF_K + st * KSTG) + (uint32_t)(frow * AQP + fcol) * 2;
        const uint32_t vbase = smem_u32(smem + OFF_V + st * VSTG) + (uint32_t)(frow * AVP + fcol) * 2;

        // ---- S = Q @ K^T : 8 private 16x8 accumulators ----
        float sacc[8][4];
        #pragma unroll
        for (int n = 0; n < 8; n++)
            #pragma unroll
            for (int e = 0; e < 4; e++) sacc[n][e] = 0.0f;
        #pragma unroll
        for (int kk = 0; kk < 8; kk++) {
            uint32_t a0, a1, a2, a3;
            ldsm4(a0, a1, a2, a3, qbase + (uint32_t)(kk * 16) * 2);
            #pragma unroll
            for (int np = 0; np < 4; np++) {
                uint32_t b0, b1, b2, b3;
                ldsm4(b0, b1, b2, b3, kbase + (uint32_t)(np * 16 * AQP + kk * 16) * 2);
                mma16816(sacc[2 * np],     a0, a1, a2, a3, b0, b1);
                mma16816(sacc[2 * np + 1], a0, a1, a2, a3, b2, b3);
            }
        }

        // ---- exp + causal mask + rowsum, build P fragments (registers only) ----
        uint32_t pa[16];
        #pragma unroll
        for (int n = 0; n < 8; n++) {
            const int colb = kt * 64 + n * 8 + ce;
            float s0 = (colb     <= r0g)     ? __expf(sacc[n][0]) : 0.0f;
            float s1 = (colb + 1 <= r0g)     ? __expf(sacc[n][1]) : 0.0f;
            float s2 = (colb     <= r0g + 8) ? __expf(sacc[n][2]) : 0.0f;
            float s3 = (colb + 1 <= r0g + 8) ? __expf(sacc[n][3]) : 0.0f;
            rsum0 += s0 + s1;
            rsum1 += s2 + s3;
            __half2 h01 = __floats2half2_rn(s0, s1);
            __half2 h23 = __floats2half2_rn(s2, s3);
            pa[n * 2]     = *reinterpret_cast<uint32_t*>(&h01);
            pa[n * 2 + 1] = *reinterpret_cast<uint32_t*>(&h23);
        }

        // ---- O += P @ V^T (A = P fragments, layout identity) ----
        #pragma unroll
        for (int j = 0; j < 4; j++) {
            const uint32_t a0 = pa[4 * j], a1 = pa[4 * j + 1];
            const uint32_t a2 = pa[4 * j + 2], a3 = pa[4 * j + 3];
            #pragma unroll
            for (int dp = 0; dp < 8; dp++) {
                uint32_t b0, b1, b2, b3;
                ldsm4(b0, b1, b2, b3, vbase + (uint32_t)(dp * 16 * AVP + j * 16) * 2);
                mma16816(oacc[2 * dp],     a0, a1, a2, a3, b0, b1);
                mma16816(oacc[2 * dp + 1], a0, a1, a2, a3, b2, b3);
            }
        }
        __syncthreads();                          // all warps done with stage st
        if (kt + 2 < nkt) load_kv(kt + 2, st);    // prefetch into freed stage
        asm volatile("cp.async.commit_group;" ::: "memory");
    }

    // ---- normalize and write ctx[b, t, h*DH + d] ----
    rsum0 += __shfl_xor_sync(0xffffffffu, rsum0, 1);
    rsum0 += __shfl_xor_sync(0xffffffffu, rsum0, 2);
    rsum1 += __shfl_xor_sync(0xffffffffu, rsum1, 1);
    rsum1 += __shfl_xor_sync(0xffffffffu, rsum1, 2);
    const float inv0 = 1.0f / rsum0;
    const float inv1 = 1.0f / rsum1;
    float* base0 = ctx + ((size_t)(b * SEQ + r0g)) * EMB + h * DH + ce;
    float* base1 = base0 + (size_t)8 * EMB;
    #pragma unroll
    for (int dn = 0; dn < 16; dn++) {
        float2 v0 = make_float2(oacc[dn][0] * inv0, oacc[dn][1] * inv0);
        float2 v1 = make_float2(oacc[dn][2] * inv1, oacc[dn][3] * inv1);
        *reinterpret_cast<float2*>(base0 + dn * 8) = v0;
        *reinterpret_cast<float2*>(base1 + dn * 8) = v1;
    }
}

// ---------------- block reductions ----------------
__device__ __forceinline__ float blk_sum(float v) {
    __shared__ float sh_s[32];
    __shared__ float tot_s;
    int lane = threadIdx.x & 31, w = threadIdx.x >> 5;
    #pragma unroll
    for (int o = 16; o; o >>= 1) v += __shfl_xor_sync(0xffffffffu, v, o);
    if (lane == 0) sh_s[w] = v;
    __syncthreads();
    if (threadIdx.x == 0) {
        float r = 0.f; int nw = blockDim.x >> 5;
        for (int i = 0; i < nw; i++) r += sh_s[i];
        tot_s = r;
    }
    __syncthreads();
    float r = tot_s;
    __syncthreads();
    return r;
}

// ---------------- conversions / norms ----------------
__global__ void f2h_k(const float* __restrict__ in, __half* __restrict__ out) {
    const int stride = gridDim.x * blockDim.x * 4;
    int base = (blockIdx.x * blockDim.x + threadIdx.x) * 4;
    #pragma unroll
    for (int r = 0; r < 4; r++) {
        int i = base + r * stride;
        float4 v = *reinterpret_cast<const float4*>(in + i);
        __half2 h[2];
        h[0] = __floats2half2_rn(v.x, v.y);
        h[1] = __floats2half2_rn(v.z, v.w);
        *reinterpret_cast<uint2*>(out + i) = *reinterpret_cast<uint2*>(h);
    }
}

struct W7 { const float* p[7]; };
__global__ void f2h7_k(W7 ws, __half* __restrict__ out) {
    const int plane = blockIdx.y;
    const float* in = ws.p[plane];
    __half* o = out + (size_t)plane * EMB * EMB;
    const int stride = gridDim.x * blockDim.x * 4;
    int base = (blockIdx.x * blockDim.x + threadIdx.x) * 4;
    #pragma unroll
    for (int r = 0; r < 4; r++) {
        int i = base + r * stride;
        float4 v = *reinterpret_cast<const float4*>(in + i);
        __half2 h[2];
        h[0] = __floats2half2_rn(v.x, v.y);
        h[1] = __floats2half2_rn(v.z, v.w);
        *reinterpret_cast<uint2*>(o + i) = *reinterpret_cast<uint2*>(h);
    }
}

__global__ void layernorm_h(const float* __restrict__ in, __half* __restrict__ out,
                            const float* __restrict__ g, const float* __restrict__ b) {
    const float* row = in + (size_t)blockIdx.x * EMB;
    __half* orow = out + (size_t)blockIdx.x * EMB;
    __shared__ float buf[EMB];
    float s = 0.f;
    for (int i = threadIdx.x; i < EMB; i += blockDim.x) { float v = row[i]; buf[i] = v; s += v; }
    const float mu = blk_sum(s) * (1.0f / EMB);
    float sq = 0.f;
    for (int i = threadIdx.x; i < EMB; i += blockDim.x) { float d = buf[i] - mu; sq += d * d; }
    const float var = blk_sum(sq) * (1.0f / EMB);
    const float inv = rsqrtf(var + 1e-5f);
    for (int i = threadIdx.x; i < EMB; i += blockDim.x)
        orow[i] = __float2half_rn((buf[i] - mu) * inv * g[i] + b[i]);
}

// x := rmsnorm(x) (fp32, residual base) and xh := half(x)
__global__ void rmsnorm_dual(float* __restrict__ x, __half* __restrict__ xh,
                             const float* __restrict__ g) {
    float* row = x + (size_t)blockIdx.x * EMB;
    __half* orow = xh + (size_t)blockIdx.x * EMB;
    __shared__ float buf[EMB];
    float ss = 0.f;
    for (int i = threadIdx.x; i < EMB; i += blockDim.x) { float v = row[i]; buf[i] = v; ss += v * v; }
    ss = blk_sum(ss);
    const float sc = rsqrtf(ss * (1.0f / EMB) + 1e-6f);
    for (int i = threadIdx.x; i < EMB; i += blockDim.x) {
        float r = g[i] * buf[i] * sc;
        row[i] = r;
        orow[i] = __float2half_rn(r);
    }
}

// out = x2 + mlp_rms_g * g * rsqrt(mean(g^2)+eps),  g = w*sigmoid(beta*w)*u  (half w,u)
__global__ void final_k(const float* __restrict__ x2, const __half* __restrict__ wv,
                        const __half* __restrict__ uv, const float* __restrict__ beta,
                        const float* __restrict__ gamma, float* __restrict__ out) {
    const size_t r = blockIdx.x;
    const float bet = beta[0];
    const __half* wrow = wv + r * EMB;
    const __half* urow = uv + r * EMB;
    __shared__ float buf[EMB];
    float ss = 0.f;
    for (int i = threadIdx.x; i < EMB; i += blockDim.x) {
        float wq = __half2float(wrow[i]);
        float s = 1.0f / (1.0f + __expf(-bet * wq));
        float gq = wq * s * __half2float(urow[i]);
        buf[i] = gq; ss += gq * gq;
    }
    ss = blk_sum(ss);
    const float sc = rsqrtf(ss * (1.0f / EMB) + 1e-6f);
    for (int i = threadIdx.x; i < EMB; i += blockDim.x)
        out[r * EMB + i] = x2[r * EMB + i] + gamma[i] * buf[i] * sc;
}

// ---------------- launcher ----------------
extern "C" void kernel_launch(void* const* d_in, const int* in_sizes, int n_in,
                              void* d_out, int out_size) {
    const float* x     = (const float*)d_in[0];
    const float* Wq    = (const float*)d_in[1];
    const float* Wk    = (const float*)d_in[2];
    const float* Wv    = (const float*)d_in[3];
    const float* Wo    = (const float*)d_in[4];
    const float* ln_g  = (const float*)d_in[5];
    const float* ln_b  = (const float*)d_in[6];
    const float* rms_g = (const float*)d_in[7];
    const float* W0    = (const float*)d_in[8];
    const float* swW   = (const float*)d_in[9];
    const float* swV   = (const float*)d_in[10];
    const float* swb   = (const float*)d_in[11];
    const float* mrg   = (const float*)d_in[12];
    float* out = (float*)d_out;

    __half *xh, *wh, *qkv, *vp, *cth, *x2h, *hh, *wuh;
    float *ctx, *xa;
    cudaGetSymbolAddress((void**)&xh,   g_xh);
    cudaGetSymbolAddress((void**)&wh,   g_wh);
    cudaGetSymbolAddress((void**)&qkv,  g_qkvh);
    cudaGetSymbolAddress((void**)&vp,   g_vp);
    cudaGetSymbolAddress((void**)&ctx,  g_ctx);
    cudaGetSymbolAddress((void**)&cth,  g_cth);
    cudaGetSymbolAddress((void**)&xa,   g_xa);
    cudaGetSymbolAddress((void**)&x2h,  g_x2h);
    cudaGetSymbolAddress((void**)&hh,   g_hh);
    cudaGetSymbolAddress((void**)&wuh,  g_wuh);

    __half* qh = qkv + 0 * PLANE;
    __half* kh = qkv + 1 * PLANE;
    __half* wvh = wuh + 0 * PLANE;
    __half* uvh = wuh + 1 * PLANE;
    const long long NW = (long long)EMB * EMB;

    cudaFuncSetAttribute(gemm_h<2,false>, cudaFuncAttributeMaxDynamicSharedMemorySize, SMEM_GEMM);
    cudaFuncSetAttribute(gemm_h<0,true >, cudaFuncAttributeMaxDynamicSharedMemorySize, SMEM_GEMM);
    cudaFuncSetAttribute(gemm_h<1,false>, cudaFuncAttributeMaxDynamicSharedMemorySize, SMEM_GEMM);
    cudaFuncSetAttribute(attn_reg128,     cudaFuncAttributeMaxDynamicSharedMemorySize, SMEM_ATT);

    const float scale = 0.08838834764831845f;  // 1/sqrt(128)
    const int NEW = MTOT * EMB;                // 8,388,608
    dim3 blk(256);

    // fp32 -> fp16 operand conversions (ILP-4 grid-stride)
    f2h_k<<<NEW / 4096, 256>>>(x, xh);
    W7 ws; ws.p[0]=Wq; ws.p[1]=Wk; ws.p[2]=Wv; ws.p[3]=Wo; ws.p[4]=W0; ws.p[5]=swW; ws.p[6]=swV;
    f2h7_k<<<dim3(NW / 4096, 7), 256>>>(ws, wh);

    // merged QKV projection: z=0 q head-split, z=1 k scaled head-split,
    // z=2 v transposed straight into vp (repack fused)
    dim3 gqkv(EMB / BN, MTOT / BM, 3);         // (16,32,3)
    gemm_h<2,false><<<gqkv, blk, SMEM_GEMM>>>(64,
        xh, EMB, 0, wh, EMB, EMB, nullptr, qkv, EMB, vp, nullptr, 1.0f, scale, 0);

    // FA2-style fused attention (register softmax), normalized fp32 ctx
    attn_reg128<<<512, blk, SMEM_ATT>>>(qh, kh, vp, ctx);

    layernorm_h<<<MTOT, 256>>>(ctx, cth, ln_g, ln_b);

    // xa = x + cth @ Wo^T (fp32, residual fused via accumulator init)
    dim3 gp(EMB / BN, MTOT / BM, 1);           // (16,32,1)
    gemm_h<0,true><<<gp, blk, SMEM_GEMM>>>(64,
        cth, EMB, 0, wh + 3 * NW, EMB, 0, xa, nullptr, EMB, nullptr, x, 1.0f, 1.0f, 0);

    rmsnorm_dual<<<MTOT, 256>>>(xa, x2h, rms_g);

    // h = x2 @ W0^T (half out)
    gemm_h<1,false><<<gp, blk, SMEM_GEMM>>>(64,
        x2h, EMB, 0, wh + 4 * NW, EMB, 0, nullptr, hh, EMB, nullptr, nullptr, 1.0f, 1.0f, 0);

    // merged swW/swV: z selects weight plane + half output plane
    dim3 gsw(EMB / BN, MTOT / BM, 2);          // (16,32,2)
    gemm_h<1,false><<<gsw, blk, SMEM_GEMM>>>(64,
        hh, EMB, 0, wh + 5 * NW, EMB, EMB, nullptr, wuh, EMB, nullptr, nullptr, 1.0f, 1.0f,
        (long long)PLANE);

    final_k<<<MTOT, 256>>>(xa, wvh, uvh, swb, mrg, out);   // swiglu + rmsnorm + residual
}

// round 15
// speedup vs baseline: 1.1981x; 1.0429x over previous
#include <cuda_runtime.h>
#include <cuda_fp16.h>
#include <mma.h>
#include <cstdint>

using namespace nvcuda;

#define SEQ 2048
#define EMB 2048
#define NB  2
#define NH  16
#define DH  128
#define MTOT (NB*SEQ)   // 4096
#define PLANE ((size_t)MTOT*EMB)

// ---------------- scratch (static device globals) ----------------
__device__ __half g_xh  [MTOT*EMB];
__device__ __half g_wh  [7][EMB*EMB];       // wq,wk,wv,wo,w0,sww,swv (contiguous)
__device__ __half g_qkvh[2][MTOT*EMB];      // plane0: qh [bh,t,d]; 1: kh [bh,s,d]
__device__ __half g_vp  [MTOT*EMB];         // [bh, d, s] (written by QKV epilogue)
__device__ float  g_ctx [MTOT*EMB];         // attention output (normalized fp32)
__device__ __half g_cth [MTOT*EMB];
__device__ float  g_xa  [MTOT*EMB];
__device__ __half g_x2h [MTOT*EMB];
__device__ __half g_hh  [MTOT*EMB];
__device__ __half g_wuh [2][MTOT*EMB];      // plane0: w, plane1: u (fp16)

__device__ __forceinline__ uint32_t smem_u32(const void* p) {
    uint32_t a;
    asm("{ .reg .u64 t; cvta.to.shared.u64 t, %1; cvt.u32.u64 %0, t; }" : "=r"(a) : "l"(p));
    return a;
}
__device__ __forceinline__ void ldsm4(uint32_t& r0, uint32_t& r1, uint32_t& r2, uint32_t& r3,
                                      uint32_t addr) {
    asm volatile("ldmatrix.sync.aligned.m8n8.x4.shared.b16 {%0,%1,%2,%3}, [%4];"
                 : "=r"(r0), "=r"(r1), "=r"(r2), "=r"(r3) : "r"(addr));
}
__device__ __forceinline__ void mma16816(float* c, uint32_t a0, uint32_t a1, uint32_t a2,
                                         uint32_t a3, uint32_t b0, uint32_t b1) {
    asm volatile("mma.sync.aligned.m16n8k16.row.col.f32.f16.f16.f32 "
                 "{%0,%1,%2,%3}, {%4,%5,%6,%7}, {%8,%9}, {%0,%1,%2,%3};"
                 : "+f"(c[0]), "+f"(c[1]), "+f"(c[2]), "+f"(c[3])
                 : "r"(a0), "r"(a1), "r"(a2), "r"(a3), "r"(b0), "r"(b1));
}

// ------------- fp16 wmma NT GEMM, BK=64 chunks, 2-stage cp.async ------------
// Half the chunk boundaries of BK=32; 4 kk sub-steps rolling-pipelined so
// 3/4 of LDSM groups overlap MMAs.
constexpr int BM = 128, BN = 128, PITCH = 72;          // 64 + 8 pad (halves)
constexpr int STG_BYTES   = BM * PITCH * 2;            // 18432 per operand
constexpr int STAGE_BYTES = 2 * STG_BYTES;             // 36864 (A+B)
constexpr int SMEM_GEMM   = 2 * STAGE_BYTES;           // 73728 (2 stages)

// OMODE: 0 = fp32 out (opt RES); 1 = half plain out; 2 = QKV combined
//   (z=0 q head-split, z=1 k head-split scaled, z=2 v transposed into Vp)
template<int OMODE, bool RES>
__global__ void __launch_bounds__(256, 2)
gemm_h(int nk,  // number of 64-wide k-chunks
       const __half* __restrict__ A, int lda, int zRowA,
       const __half* __restrict__ B, int ldb, int zRowB,
       float* __restrict__ C, __half* __restrict__ Ch, int ldc,
       __half* __restrict__ Vp,
       const float* __restrict__ Rres, float alphaA, float alphaB,
       long long sC)
{
    const int bn0 = blockIdx.x * BN;
    const int bm0 = blockIdx.y * BM;
    const int z = blockIdx.z;

    extern __shared__ __align__(128) char smem[];
    const int tid  = threadIdx.x;
    const int wid  = tid >> 5;
    const int lane = tid & 31;
    const int wm = (wid & 3) * 32;
    const int wn = (wid >> 2) * 64;

    const __half* Abase = A + (size_t)(z * zRowA + bm0) * lda;
    const __half* Bbase = B + (size_t)(z * zRowB + bn0) * ldb;
    const long long coff = (long long)z * sC;

    auto load_chunk = [&](int kc) {
        const int st = kc & 1;
        char* sA = smem + st * STAGE_BYTES;
        char* sB = sA + STG_BYTES;
        const __half* ag = Abase + kc * 64;
        const __half* bg = Bbase + kc * 64;
        #pragma unroll
        for (int i = 0; i < 4; i++) {            // 1024 16B segs per operand
            int idx = i * 256 + tid;
            int row = idx >> 3, seg = idx & 7;
            uint32_t da = smem_u32(sA + row * (PITCH * 2) + seg * 16);
            const __half* srca = ag + (size_t)row * lda + seg * 8;
            asm volatile("cp.async.cg.shared.global [%0], [%1], 16;" :: "r"(da), "l"(srca));
            uint32_t db = smem_u32(sB + row * (PITCH * 2) + seg * 16);
            const __half* srcb = bg + (size_t)row * ldb + seg * 8;
            asm volatile("cp.async.cg.shared.global [%0], [%1], 16;" :: "r"(db), "l"(srcb));
        }
        asm volatile("cp.async.commit_group;" ::: "memory");
    };

    wmma::fragment<wmma::accumulator, 16, 16, 16, float> acc[2][4];
    #pragma unroll
    for (int mi = 0; mi < 2; mi++)
        #pragma unroll
        for (int ni = 0; ni < 4; ni++) {
            if (RES)
                wmma::load_matrix_sync(acc[mi][ni],
                    Rres + coff + (long long)(bm0 + wm + mi * 16) * ldc + (bn0 + wn + ni * 16),
                    ldc, wmma::mem_row_major);
            else
                wmma::fill_fragment(acc[mi][ni], 0.0f);
        }

    load_chunk(0);

    for (int kc = 0; kc < nk; kc++) {
        asm volatile("cp.async.wait_group 0;" ::: "memory");
        __syncthreads();                          // single sync per 64-chunk

        const __half* sA = (const __half*)(smem + (kc & 1) * STAGE_BYTES);
        const __half* sB = sA + BM * PITCH;

        // rolling double-buffered fragments over 4 kk sub-steps
        wmma::fragment<wmma::matrix_a, 16, 16, 16, __half, wmma::row_major> af[2][2];
        wmma::fragment<wmma::matrix_b, 16, 16, 16, __half, wmma::col_major> bf[2][4];

        // load kk=0 -> buf0
        #pragma unroll
        for (int mi = 0; mi < 2; mi++)
            wmma::load_matrix_sync(af[0][mi], sA + (wm + mi * 16) * PITCH, PITCH);
        #pragma unroll
        for (int j = 0; j < 4; j++)
            wmma::load_matrix_sync(bf[0][j], sB + (wn + j * 16) * PITCH, PITCH);

        if (kc + 1 < nk) load_chunk(kc + 1);      // gmem prefetch (other stage)

        #pragma unroll
        for (int kk = 0; kk < 4; kk++) {
            const int cur = kk & 1;
            const int nxt = cur ^ 1;
            if (kk + 1 < 4) {                     // load kk+1 -> other buffer
                #pragma unroll
                for (int mi = 0; mi < 2; mi++)
                    wmma::load_matrix_sync(af[nxt][mi],
                        sA + (wm + mi * 16) * PITCH + (kk + 1) * 16, PITCH);
                #pragma unroll
                for (int j = 0; j < 4; j++)
                    wmma::load_matrix_sync(bf[nxt][j],
                        sB + (wn + j * 16) * PITCH + (kk + 1) * 16, PITCH);
            }
            #pragma unroll
            for (int mi = 0; mi < 2; mi++)
                #pragma unroll
                for (int j = 0; j < 4; j++)
                    wmma::mma_sync(acc[mi][j], af[cur][mi], bf[cur][j], acc[mi][j]);
        }
    }

    const float alpha = (OMODE == 2) ? ((z == 1) ? alphaB : alphaA) : alphaA;
    if (alpha != 1.0f) {
        #pragma unroll
        for (int mi = 0; mi < 2; mi++)
            #pragma unroll
            for (int ni = 0; ni < 4; ni++)
                #pragma unroll
                for (int e = 0; e < acc[mi][ni].num_elements; e++)
                    acc[mi][ni].x[e] *= alpha;
    }

    if (OMODE == 0) {
        float* Cp = C + coff;
        #pragma unroll
        for (int mi = 0; mi < 2; mi++)
            #pragma unroll
            for (int ni = 0; ni < 4; ni++)
                wmma::store_matrix_sync(
                    Cp + (long long)(bm0 + wm + mi * 16) * ldc + (bn0 + wn + ni * 16),
                    acc[mi][ni], ldc, wmma::mem_row_major);
    } else {
        __syncthreads();                          // all MMAs done before smem reuse
        float* stg = (float*)smem + wid * 320;    // 16x16 tile, pitch 20
        __half* Cp = (OMODE == 2) ? (Ch + (size_t)z * PLANE) : Ch;
        const bool vmode = (OMODE == 2) && (z == 2);
        #pragma unroll
        for (int mi = 0; mi < 2; mi++)
            #pragma unroll
            for (int ni = 0; ni < 4; ni++) {
                wmma::store_matrix_sync(stg, acc[mi][ni], 20, wmma::mem_row_major);
                __syncwarp();
                if (vmode) {
                    // tile = 16 tokens x 16 heads at fixed d; transpose to vp[bh][d][s]
                    const int c  = lane >> 1;      // head within tile
                    const int hf = lane & 1;       // token half (8 each)
                    __half hv8[8];
                    #pragma unroll
                    for (int rr = 0; rr < 8; rr++)
                        hv8[rr] = __float2half_rn(stg[(hf * 8 + rr) * 20 + c]);
                    const int grow0 = bm0 + wm + mi * 16;
                    const int bb = grow0 >> 11, t0 = grow0 & 2047;
                    const int d = (bn0 + wn + ni * 16) >> 4;
                    __half* dstv = Vp + ((size_t)((bb << 4) + c) * DH + d) * SEQ + t0 + hf * 8;
                    *reinterpret_cast<uint4*>(dstv) = *reinterpret_cast<uint4*>(hv8);
                } else {
                    const int r  = lane >> 1;
                    const int cb = (lane & 1) * 8;
                    __half2 hv[4];
                    #pragma unroll
                    for (int j = 0; j < 4; j++)
                        hv[j] = __floats2half2_rn(stg[r * 20 + cb + 2 * j],
                                                  stg[r * 20 + cb + 2 * j + 1]);
                    const int grow = bm0 + wm + mi * 16 + r;
                    const int gcol = wn + ni * 16 + cb;
                    __half* dst;
                    if (OMODE == 2) {              // q/k head-split [bh, t, d]
                        const int b = grow >> 11, tt = grow & 2047;
                        dst = Cp + ((size_t)((b << 4) + (bn0 >> 7)) * SEQ + tt) * DH + gcol;
                    } else {
                        dst = Cp + coff + (size_t)grow * ldc + bn0 + gcol;
                    }
                    *reinterpret_cast<uint4*>(dst) = *reinterpret_cast<uint4*>(hv);
                }
                __syncwarp();
            }
    }
}

// ------ FA2-style fused attention: register softmax, mma.sync, dbl-buf K/V ----
constexpr int AQP = 136;                       // Q/K pitch (halves)
constexpr int AVP = 72;                        // V pitch (halves)
constexpr int KSTG = 64 * AQP * 2;             // 17408
constexpr int VSTG = 128 * AVP * 2;            // 18432
constexpr int OFF_K = 128 * AQP * 2;           // 34816 (after Q)
constexpr int OFF_V = OFF_K + 2 * KSTG;        // 69632
constexpr int SMEM_ATT = OFF_V + 2 * VSTG;     // 106496

__global__ void __launch_bounds__(256, 2)
attn_reg128(const __half* __restrict__ qh,   // [bh, t, d]
            const __half* __restrict__ kh,   // [bh, s, d] (pre-scaled)
            const __half* __restrict__ vp,   // [bh, d, s]
            float* __restrict__ ctx)         // [b, t, E] normalized fp32
{
    extern __shared__ __align__(128) char smem[];
    __half* Qs = (__half*)smem;

    const int bh = blockIdx.x & 31;
    const int qt = 15 - (blockIdx.x >> 5);     // heavy q-tiles first
    const int b = bh >> 4, h = bh & 15;
    const int tid  = threadIdx.x;
    const int wid  = tid >> 5;
    const int lane = tid & 31;
    const int nkt = 2 * qt + 2;

    auto load_kv = [&](int kt, int st) {       // K 64x128 + V 128x64 into stage st
        const __half* kg = kh + ((size_t)bh * SEQ + kt * 64) * DH;
        const __half* vg = vp + (size_t)bh * DH * SEQ + kt * 64;
        char* Kst = smem + OFF_K + st * KSTG;
        char* Vst = smem + OFF_V + st * VSTG;
        #pragma unroll
        for (int i = 0; i < 4; i++) {
            int s = i * 256 + tid;
            int rk = s >> 4, ck = s & 15;
            uint32_t dk = smem_u32(Kst + (rk * AQP + ck * 8) * 2);
            asm volatile("cp.async.cg.shared.global [%0], [%1], 16;"
                         :: "r"(dk), "l"(kg + (size_t)rk * DH + ck * 8));
            int rv = s >> 3, cv = s & 7;
            uint32_t dv = smem_u32(Vst + (rv * AVP + cv * 8) * 2);
            asm volatile("cp.async.cg.shared.global [%0], [%1], 16;"
                         :: "r"(dv), "l"(vg + (size_t)rv * SEQ + cv * 8));
        }
    };

    // prologue group 1: Q + KV(0) stage 0
    {
        const __half* qg = qh + ((size_t)bh * SEQ + qt * 128) * DH;
        #pragma unroll
        for (int i = 0; i < 8; i++) {
            int s = i * 256 + tid;
            int row = s >> 4, seg = s & 15;
            uint32_t dst = smem_u32(Qs + row * AQP + seg * 8);
            asm volatile("cp.async.cg.shared.global [%0], [%1], 16;"
                         :: "r"(dst), "l"(qg + (size_t)row * DH + seg * 8));
        }
        load_kv(0, 0);
        asm volatile("cp.async.commit_group;" ::: "memory");
    }
    // prologue group 2: KV(1) stage 1
    if (nkt > 1) load_kv(1, 1);
    asm volatile("cp.async.commit_group;" ::: "memory");

    float oacc[16][4];
    #pragma unroll
    for (int n = 0; n < 16; n++)
        #pragma unroll
        for (int e = 0; e < 4; e++) oacc[n][e] = 0.0f;
    float rsum0 = 0.0f, rsum1 = 0.0f;

    const uint32_t qbase = smem_u32(Qs + (wid * 16 + (lane & 15)) * AQP + (lane >> 4) * 8);
    const int frow = ((lane >> 4) << 3) + (lane & 7);      // fragment row
    const int fcol = ((lane >> 3) & 1) * 8;                // fragment col offset
    const int r0g = qt * 128 + wid * 16 + (lane >> 2);     // global q row (c0,c1)
    const int ce  = (lane & 3) * 2;                        // col-in-tile even index

    for (int kt = 0; kt < nkt; kt++) {
        asm volatile("cp.async.wait_group 1;" ::: "memory");   // KV(kt) landed
        __syncthreads();
        const int st = kt & 1;
        const uint32_t kbase = smem_u32(smem + OFF_K + st * KSTG) + (uint32_t)(frow * AQP + fcol) * 2;
        const uint32_t vbase = smem_u32(smem + OFF_V + st * VSTG) + (uint32_t)(frow * AVP + fcol) * 2;

        // ---- S = Q @ K^T : 8 private 16x8 accumulators ----
        float sacc[8][4];
        #pragma unroll
        for (int n = 0; n < 8; n++)
            #pragma unroll
            for (int e = 0; e < 4; e++) sacc[n][e] = 0.0f;
        #pragma unroll
        for (int kk = 0; kk < 8; kk++) {
            uint32_t a0, a1, a2, a3;
            ldsm4(a0, a1, a2, a3, qbase + (uint32_t)(kk * 16) * 2);
            #pragma unroll
            for (int np = 0; np < 4; np++) {
                uint32_t b0, b1, b2, b3;
                ldsm4(b0, b1, b2, b3, kbase + (uint32_t)(np * 16 * AQP + kk * 16) * 2);
                mma16816(sacc[2 * np],     a0, a1, a2, a3, b0, b1);
                mma16816(sacc[2 * np + 1], a0, a1, a2, a3, b2, b3);
            }
        }

        // ---- exp + causal mask + rowsum, build P fragments (registers only) ----
        uint32_t pa[16];
        #pragma unroll
        for (int n = 0; n < 8; n++) {
            const int colb = kt * 64 + n * 8 + ce;
            float s0 = (colb     <= r0g)     ? __expf(sacc[n][0]) : 0.0f;
            float s1 = (colb + 1 <= r0g)     ? __expf(sacc[n][1]) : 0.0f;
            float s2 = (colb     <= r0g + 8) ? __expf(sacc[n][2]) : 0.0f;
            float s3 = (colb + 1 <= r0g + 8) ? __expf(sacc[n][3]) : 0.0f;
            rsum0 += s0 + s1;
            rsum1 += s2 + s3;
            __half2 h01 = __floats2half2_rn(s0, s1);
            __half2 h23 = __floats2half2_rn(s2, s3);
            pa[n * 2]     = *reinterpret_cast<uint32_t*>(&h01);
            pa[n * 2 + 1] = *reinterpret_cast<uint32_t*>(&h23);
        }

        // ---- O += P @ V^T (A = P fragments, layout identity) ----
        #pragma unroll
        for (int j = 0; j < 4; j++) {
            const uint32_t a0 = pa[4 * j], a1 = pa[4 * j + 1];
            const uint32_t a2 = pa[4 * j + 2], a3 = pa[4 * j + 3];
            #pragma unroll
            for (int dp = 0; dp < 8; dp++) {
                uint32_t b0, b1, b2, b3;
                ldsm4(b0, b1, b2, b3, vbase + (uint32_t)(dp * 16 * AVP + j * 16) * 2);
                mma16816(oacc[2 * dp],     a0, a1, a2, a3, b0, b1);
                mma16816(oacc[2 * dp + 1], a0, a1, a2, a3, b2, b3);
            }
        }
        __syncthreads();                          // all warps done with stage st
        if (kt + 2 < nkt) load_kv(kt + 2, st);    // prefetch into freed stage
        asm volatile("cp.async.commit_group;" ::: "memory");
    }

    // ---- normalize and write ctx[b, t, h*DH + d] ----
    rsum0 += __shfl_xor_sync(0xffffffffu, rsum0, 1);
    rsum0 += __shfl_xor_sync(0xffffffffu, rsum0, 2);
    rsum1 += __shfl_xor_sync(0xffffffffu, rsum1, 1);
    rsum1 += __shfl_xor_sync(0xffffffffu, rsum1, 2);
    const float inv0 = 1.0f / rsum0;
    const float inv1 = 1.0f / rsum1;
    float* base0 = ctx + ((size_t)(b * SEQ + r0g)) * EMB + h * DH + ce;
    float* base1 = base0 + (size_t)8 * EMB;
    #pragma unroll
    for (int dn = 0; dn < 16; dn++) {
        float2 v0 = make_float2(oacc[dn][0] * inv0, oacc[dn][1] * inv0);
        float2 v1 = make_float2(oacc[dn][2] * inv1, oacc[dn][3] * inv1);
        *reinterpret_cast<float2*>(base0 + dn * 8) = v0;
        *reinterpret_cast<float2*>(base1 + dn * 8) = v1;
    }
}

// ---------------- block reductions ----------------
__device__ __forceinline__ float blk_sum(float v) {
    __shared__ float sh_s[32];
    __shared__ float tot_s;
    int lane = threadIdx.x & 31, w = threadIdx.x >> 5;
    #pragma unroll
    for (int o = 16; o; o >>= 1) v += __shfl_xor_sync(0xffffffffu, v, o);
    if (lane == 0) sh_s[w] = v;
    __syncthreads();
    if (threadIdx.x == 0) {
        float r = 0.f; int nw = blockDim.x >> 5;
        for (int i = 0; i < nw; i++) r += sh_s[i];
        tot_s = r;
    }
    __syncthreads();
    float r = tot_s;
    __syncthreads();
    return r;
}

// ---------------- conversions / norms ----------------
__global__ void f2h_k(const float* __restrict__ in, __half* __restrict__ out) {
    const int stride = gridDim.x * blockDim.x * 4;
    int base = (blockIdx.x * blockDim.x + threadIdx.x) * 4;
    #pragma unroll
    for (int r = 0; r < 4; r++) {
        int i = base + r * stride;
        float4 v = *reinterpret_cast<const float4*>(in + i);
        __half2 h[2];
        h[0] = __floats2half2_rn(v.x, v.y);
        h[1] = __floats2half2_rn(v.z, v.w);
        *reinterpret_cast<uint2*>(out + i) = *reinterpret_cast<uint2*>(h);
    }
}

struct W7 { const float* p[7]; };
__global__ void f2h7_k(W7 ws, __half* __restrict__ out) {
    const int plane = blockIdx.y;
    const float* in = ws.p[plane];
    __half* o = out + (size_t)plane * EMB * EMB;
    const int stride = gridDim.x * blockDim.x * 4;
    int base = (blockIdx.x * blockDim.x + threadIdx.x) * 4;
    #pragma unroll
    for (int r = 0; r < 4; r++) {
        int i = base + r * stride;
        float4 v = *reinterpret_cast<const float4*>(in + i);
        __half2 h[2];
        h[0] = __floats2half2_rn(v.x, v.y);
        h[1] = __floats2half2_rn(v.z, v.w);
        *reinterpret_cast<uint2*>(o + i) = *reinterpret_cast<uint2*>(h);
    }
}

__global__ void layernorm_h(const float* __restrict__ in, __half* __restrict__ out,
                            const float* __restrict__ g, const float* __restrict__ b) {
    const float* row = in + (size_t)blockIdx.x * EMB;
    __half* orow = out + (size_t)blockIdx.x * EMB;
    __shared__ float buf[EMB];
    float s = 0.f;
    for (int i = threadIdx.x; i < EMB; i += blockDim.x) { float v = row[i]; buf[i] = v; s += v; }
    const float mu = blk_sum(s) * (1.0f / EMB);
    float sq = 0.f;
    for (int i = threadIdx.x; i < EMB; i += blockDim.x) { float d = buf[i] - mu; sq += d * d; }
    const float var = blk_sum(sq) * (1.0f / EMB);
    const float inv = rsqrtf(var + 1e-5f);
    for (int i = threadIdx.x; i < EMB; i += blockDim.x)
        orow[i] = __float2half_rn((buf[i] - mu) * inv * g[i] + b[i]);
}

// x := rmsnorm(x) (fp32, residual base) and xh := half(x)
__global__ void rmsnorm_dual(float* __restrict__ x, __half* __restrict__ xh,
                             const float* __restrict__ g) {
    float* row = x + (size_t)blockIdx.x * EMB;
    __half* orow = xh + (size_t)blockIdx.x * EMB;
    __shared__ float buf[EMB];
    float ss = 0.f;
    for (int i = threadIdx.x; i < EMB; i += blockDim.x) { float v = row[i]; buf[i] = v; ss += v * v; }
    ss = blk_sum(ss);
    const float sc = rsqrtf(ss * (1.0f / EMB) + 1e-6f);
    for (int i = threadIdx.x; i < EMB; i += blockDim.x) {
        float r = g[i] * buf[i] * sc;
        row[i] = r;
        orow[i] = __float2half_rn(r);
    }
}

// out = x2 + mlp_rms_g * g * rsqrt(mean(g^2)+eps),  g = w*sigmoid(beta*w)*u  (half w,u)
__global__ void final_k(const float* __restrict__ x2, const __half* __restrict__ wv,
                        const __half* __restrict__ uv, const float* __restrict__ beta,
                        const float* __restrict__ gamma, float* __restrict__ out) {
    const size_t r = blockIdx.x;
    const float bet = beta[0];
    const __half* wrow = wv + r * EMB;
    const __half* urow = uv + r * EMB;
    __shared__ float buf[EMB];
    float ss = 0.f;
    for (int i = threadIdx.x; i < EMB; i += blockDim.x) {
        float wq = __half2float(wrow[i]);
        float s = 1.0f / (1.0f + __expf(-bet * wq));
        float gq = wq * s * __half2float(urow[i]);
        buf[i] = gq; ss += gq * gq;
    }
    ss = blk_sum(ss);
    const float sc = rsqrtf(ss * (1.0f / EMB) + 1e-6f);
    for (int i = threadIdx.x; i < EMB; i += blockDim.x)
        out[r * EMB + i] = x2[r * EMB + i] + gamma[i] * buf[i] * sc;
}

// ---------------- launcher ----------------
extern "C" void kernel_launch(void* const* d_in, const int* in_sizes, int n_in,
                              void* d_out, int out_size) {
    const float* x     = (const float*)d_in[0];
    const float* Wq    = (const float*)d_in[1];
    const float* Wk    = (const float*)d_in[2];
    const float* Wv    = (const float*)d_in[3];
    const float* Wo    = (const float*)d_in[4];
    const float* ln_g  = (const float*)d_in[5];
    const float* ln_b  = (const float*)d_in[6];
    const float* rms_g = (const float*)d_in[7];
    const float* W0    = (const float*)d_in[8];
    const float* swW   = (const float*)d_in[9];
    const float* swV   = (const float*)d_in[10];
    const float* swb   = (const float*)d_in[11];
    const float* mrg   = (const float*)d_in[12];
    float* out = (float*)d_out;

    __half *xh, *wh, *qkv, *vp, *cth, *x2h, *hh, *wuh;
    float *ctx, *xa;
    cudaGetSymbolAddress((void**)&xh,   g_xh);
    cudaGetSymbolAddress((void**)&wh,   g_wh);
    cudaGetSymbolAddress((void**)&qkv,  g_qkvh);
    cudaGetSymbolAddress((void**)&vp,   g_vp);
    cudaGetSymbolAddress((void**)&ctx,  g_ctx);
    cudaGetSymbolAddress((void**)&cth,  g_cth);
    cudaGetSymbolAddress((void**)&xa,   g_xa);
    cudaGetSymbolAddress((void**)&x2h,  g_x2h);
    cudaGetSymbolAddress((void**)&hh,   g_hh);
    cudaGetSymbolAddress((void**)&wuh,  g_wuh);

    __half* qh = qkv + 0 * PLANE;
    __half* kh = qkv + 1 * PLANE;
    __half* wvh = wuh + 0 * PLANE;
    __half* uvh = wuh + 1 * PLANE;
    const long long NW = (long long)EMB * EMB;

    cudaFuncSetAttribute(gemm_h<2,false>, cudaFuncAttributeMaxDynamicSharedMemorySize, SMEM_GEMM);
    cudaFuncSetAttribute(gemm_h<0,true >, cudaFuncAttributeMaxDynamicSharedMemorySize, SMEM_GEMM);
    cudaFuncSetAttribute(gemm_h<1,false>, cudaFuncAttributeMaxDynamicSharedMemorySize, SMEM_GEMM);
    cudaFuncSetAttribute(attn_reg128,     cudaFuncAttributeMaxDynamicSharedMemorySize, SMEM_ATT);

    const float scale = 0.08838834764831845f;  // 1/sqrt(128)
    const int NEW = MTOT * EMB;                // 8,388,608
    dim3 blk(256);

    // fp32 -> fp16 operand conversions (ILP-4 grid-stride)
    f2h_k<<<NEW / 4096, 256>>>(x, xh);
    W7 ws; ws.p[0]=Wq; ws.p[1]=Wk; ws.p[2]=Wv; ws.p[3]=Wo; ws.p[4]=W0; ws.p[5]=swW; ws.p[6]=swV;
    f2h7_k<<<dim3(NW / 4096, 7), 256>>>(ws, wh);

    // merged QKV projection: z=0 q head-split, z=1 k scaled head-split,
    // z=2 v transposed straight into vp (repack fused)
    dim3 gqkv(EMB / BN, MTOT / BM, 3);         // (16,32,3)
    gemm_h<2,false><<<gqkv, blk, SMEM_GEMM>>>(32,
        xh, EMB, 0, wh, EMB, EMB, nullptr, qkv, EMB, vp, nullptr, 1.0f, scale, 0);

    // FA2-style fused attention (register softmax), normalized fp32 ctx
    attn_reg128<<<512, blk, SMEM_ATT>>>(qh, kh, vp, ctx);

    layernorm_h<<<MTOT, 256>>>(ctx, cth, ln_g, ln_b);

    // xa = x + cth @ Wo^T (fp32, residual fused via accumulator init)
    dim3 gp(EMB / BN, MTOT / BM, 1);           // (16,32,1)
    gemm_h<0,true><<<gp, blk, SMEM_GEMM>>>(32,
        cth, EMB, 0, wh + 3 * NW, EMB, 0, xa, nullptr, EMB, nullptr, x, 1.0f, 1.0f, 0);

    rmsnorm_dual<<<MTOT, 256>>>(xa, x2h, rms_g);

    // h = x2 @ W0^T (half out)
    gemm_h<1,false><<<gp, blk, SMEM_GEMM>>>(32,
        x2h, EMB, 0, wh + 4 * NW, EMB, 0, nullptr, hh, EMB, nullptr, nullptr, 1.0f, 1.0f, 0);

    // merged swW/swV: z selects weight plane + half output plane
    dim3 gsw(EMB / BN, MTOT / BM, 2);          // (16,32,2)
    gemm_h<1,false><<<gsw, blk, SMEM_GEMM>>>(32,
        hh, EMB, 0, wh + 5 * NW, EMB, EMB, nullptr, wuh, EMB, nullptr, nullptr, 1.0f, 1.0f,
        (long long)PLANE);

    final_k<<<MTOT, 256>>>(xa, wvh, uvh, swb, mrg, out);   // swiglu + rmsnorm + residual
}

// round 16
// speedup vs baseline: 1.2118x; 1.0115x over previous
#include <cuda_runtime.h>
#include <cuda_fp16.h>
#include <mma.h>
#include <cstdint>

using namespace nvcuda;

#define SEQ 2048
#define EMB 2048
#define NB  2
#define NH  16
#define DH  128
#define MTOT (NB*SEQ)   // 4096
#define PLANE ((size_t)MTOT*EMB)

// ---------------- scratch (static device globals) ----------------
__device__ __half g_xh  [MTOT*EMB];
__device__ __half g_wh  [7][EMB*EMB];       // wq,wk,wv,wo,w0,sww,swv (contiguous)
__device__ __half g_qkvh[2][MTOT*EMB];      // plane0: qh [bh,t,d]; 1: kh [bh,s,d]
__device__ __half g_vp  [MTOT*EMB];         // [bh, d, s] (written by QKV epilogue)
__device__ float  g_ctx [MTOT*EMB];         // attention output (normalized fp32)
__device__ __half g_cth [MTOT*EMB];
__device__ float  g_xa  [MTOT*EMB];
__device__ __half g_x2h [MTOT*EMB];
__device__ __half g_hh  [MTOT*EMB];
__device__ __half g_wuh [2][MTOT*EMB];      // plane0: w, plane1: u (fp16)

__device__ __forceinline__ uint32_t smem_u32(const void* p) {
    uint32_t a;
    asm("{ .reg .u64 t; cvta.to.shared.u64 t, %1; cvt.u32.u64 %0, t; }" : "=r"(a) : "l"(p));
    return a;
}
__device__ __forceinline__ void ldsm4(uint32_t& r0, uint32_t& r1, uint32_t& r2, uint32_t& r3,
                                      uint32_t addr) {
    asm volatile("ldmatrix.sync.aligned.m8n8.x4.shared.b16 {%0,%1,%2,%3}, [%4];"
                 : "=r"(r0), "=r"(r1), "=r"(r2), "=r"(r3) : "r"(addr));
}
__device__ __forceinline__ void mma16816(float* c, uint32_t a0, uint32_t a1, uint32_t a2,
                                         uint32_t a3, uint32_t b0, uint32_t b1) {
    asm volatile("mma.sync.aligned.m16n8k16.row.col.f32.f16.f16.f32 "
                 "{%0,%1,%2,%3}, {%4,%5,%6,%7}, {%8,%9}, {%0,%1,%2,%3};"
                 : "+f"(c[0]), "+f"(c[1]), "+f"(c[2]), "+f"(c[3])
                 : "r"(a0), "r"(a1), "r"(a2), "r"(a3), "r"(b0), "r"(b1));
}

// ------------- fp16 wmma NT GEMM, BK=64 chunks, 3-stage cp.async ------------
constexpr int BM = 128, BN = 128, PITCH = 72;          // 64 + 8 pad (halves)
constexpr int STG_BYTES   = BM * PITCH * 2;            // 18432 per operand
constexpr int STAGE_BYTES = 2 * STG_BYTES;             // 36864 (A+B)
constexpr int NSTG = 3;
constexpr int SMEM_GEMM   = NSTG * STAGE_BYTES;        // 110592 (occ 2: 221KB <= 228KB)

// OMODE: 0 = fp32 out (opt RES); 1 = half plain out; 2 = QKV combined
//   (z=0 q head-split, z=1 k head-split scaled, z=2 v transposed into Vp)
template<int OMODE, bool RES>
__global__ void __launch_bounds__(256, 2)
gemm_h(int nk,  // number of 64-wide k-chunks
       const __half* __restrict__ A, int lda, int zRowA,
       const __half* __restrict__ B, int ldb, int zRowB,
       float* __restrict__ C, __half* __restrict__ Ch, int ldc,
       __half* __restrict__ Vp,
       const float* __restrict__ Rres, float alphaA, float alphaB,
       long long sC)
{
    const int bn0 = blockIdx.x * BN;
    const int bm0 = blockIdx.y * BM;
    const int z = blockIdx.z;

    extern __shared__ __align__(128) char smem[];
    const int tid  = threadIdx.x;
    const int wid  = tid >> 5;
    const int lane = tid & 31;
    const int wm = (wid & 3) * 32;
    const int wn = (wid >> 2) * 64;

    const __half* Abase = A + (size_t)(z * zRowA + bm0) * lda;
    const __half* Bbase = B + (size_t)(z * zRowB + bn0) * ldb;
    const long long coff = (long long)z * sC;

    auto load_chunk = [&](int kc) {
        const int st = kc % NSTG;
        char* sA = smem + st * STAGE_BYTES;
        char* sB = sA + STG_BYTES;
        const __half* ag = Abase + kc * 64;
        const __half* bg = Bbase + kc * 64;
        #pragma unroll
        for (int i = 0; i < 4; i++) {            // 1024 16B segs per operand
            int idx = i * 256 + tid;
            int row = idx >> 3, seg = idx & 7;
            uint32_t da = smem_u32(sA + row * (PITCH * 2) + seg * 16);
            const __half* srca = ag + (size_t)row * lda + seg * 8;
            asm volatile("cp.async.cg.shared.global [%0], [%1], 16;" :: "r"(da), "l"(srca));
            uint32_t db = smem_u32(sB + row * (PITCH * 2) + seg * 16);
            const __half* srcb = bg + (size_t)row * ldb + seg * 8;
            asm volatile("cp.async.cg.shared.global [%0], [%1], 16;" :: "r"(db), "l"(srcb));
        }
        asm volatile("cp.async.commit_group;" ::: "memory");
    };

    wmma::fragment<wmma::accumulator, 16, 16, 16, float> acc[2][4];
    #pragma unroll
    for (int mi = 0; mi < 2; mi++)
        #pragma unroll
        for (int ni = 0; ni < 4; ni++) {
            if (RES)
                wmma::load_matrix_sync(acc[mi][ni],
                    Rres + coff + (long long)(bm0 + wm + mi * 16) * ldc + (bn0 + wn + ni * 16),
                    ldc, wmma::mem_row_major);
            else
                wmma::fill_fragment(acc[mi][ni], 0.0f);
        }

    load_chunk(0);
    if (nk > 1) load_chunk(1);

    for (int kc = 0; kc < nk; kc++) {
        if (kc + 1 < nk)
            asm volatile("cp.async.wait_group 1;" ::: "memory");
        else
            asm volatile("cp.async.wait_group 0;" ::: "memory");
        __syncthreads();                          // single sync per 64-chunk

        const __half* sA = (const __half*)(smem + (kc % NSTG) * STAGE_BYTES);
        const __half* sB = sA + BM * PITCH;

        // rolling double-buffered fragments over 4 kk sub-steps
        wmma::fragment<wmma::matrix_a, 16, 16, 16, __half, wmma::row_major> af[2][2];
        wmma::fragment<wmma::matrix_b, 16, 16, 16, __half, wmma::col_major> bf[2][4];

        // load kk=0 -> buf0
        #pragma unroll
        for (int mi = 0; mi < 2; mi++)
            wmma::load_matrix_sync(af[0][mi], sA + (wm + mi * 16) * PITCH, PITCH);
        #pragma unroll
        for (int j = 0; j < 4; j++)
            wmma::load_matrix_sync(bf[0][j], sB + (wn + j * 16) * PITCH, PITCH);

        if (kc + 2 < nk) load_chunk(kc + 2);      // gmem prefetch (3rd stage)

        #pragma unroll
        for (int kk = 0; kk < 4; kk++) {
            const int cur = kk & 1;
            const int nxt = cur ^ 1;
            if (kk + 1 < 4) {                     // load kk+1 -> other buffer
                #pragma unroll
                for (int mi = 0; mi < 2; mi++)
                    wmma::load_matrix_sync(af[nxt][mi],
                        sA + (wm + mi * 16) * PITCH + (kk + 1) * 16, PITCH);
                #pragma unroll
                for (int j = 0; j < 4; j++)
                    wmma::load_matrix_sync(bf[nxt][j],
                        sB + (wn + j * 16) * PITCH + (kk + 1) * 16, PITCH);
            }
            #pragma unroll
            for (int mi = 0; mi < 2; mi++)
                #pragma unroll
                for (int j = 0; j < 4; j++)
                    wmma::mma_sync(acc[mi][j], af[cur][mi], bf[cur][j], acc[mi][j]);
        }
    }

    const float alpha = (OMODE == 2) ? ((z == 1) ? alphaB : alphaA) : alphaA;
    if (alpha != 1.0f) {
        #pragma unroll
        for (int mi = 0; mi < 2; mi++)
            #pragma unroll
            for (int ni = 0; ni < 4; ni++)
                #pragma unroll
                for (int e = 0; e < acc[mi][ni].num_elements; e++)
                    acc[mi][ni].x[e] *= alpha;
    }

    if (OMODE == 0) {
        float* Cp = C + coff;
        #pragma unroll
        for (int mi = 0; mi < 2; mi++)
            #pragma unroll
            for (int ni = 0; ni < 4; ni++)
                wmma::store_matrix_sync(
                    Cp + (long long)(bm0 + wm + mi * 16) * ldc + (bn0 + wn + ni * 16),
                    acc[mi][ni], ldc, wmma::mem_row_major);
    } else {
        __syncthreads();                          // all MMAs done before smem reuse
        float* stg = (float*)smem + wid * 320;    // 16x16 tile, pitch 20
        __half* Cp = (OMODE == 2) ? (Ch + (size_t)z * PLANE) : Ch;
        const bool vmode = (OMODE == 2) && (z == 2);
        #pragma unroll
        for (int mi = 0; mi < 2; mi++)
            #pragma unroll
            for (int ni = 0; ni < 4; ni++) {
                wmma::store_matrix_sync(stg, acc[mi][ni], 20, wmma::mem_row_major);
                __syncwarp();
                if (vmode) {
                    // tile = 16 tokens x 16 heads at fixed d; transpose to vp[bh][d][s]
                    const int c  = lane >> 1;      // head within tile
                    const int hf = lane & 1;       // token half (8 each)
                    __half hv8[8];
                    #pragma unroll
                    for (int rr = 0; rr < 8; rr++)
                        hv8[rr] = __float2half_rn(stg[(hf * 8 + rr) * 20 + c]);
                    const int grow0 = bm0 + wm + mi * 16;
                    const int bb = grow0 >> 11, t0 = grow0 & 2047;
                    const int d = (bn0 + wn + ni * 16) >> 4;
                    __half* dstv = Vp + ((size_t)((bb << 4) + c) * DH + d) * SEQ + t0 + hf * 8;
                    *reinterpret_cast<uint4*>(dstv) = *reinterpret_cast<uint4*>(hv8);
                } else {
                    const int r  = lane >> 1;
                    const int cb = (lane & 1) * 8;
                    __half2 hv[4];
                    #pragma unroll
                    for (int j = 0; j < 4; j++)
                        hv[j] = __floats2half2_rn(stg[r * 20 + cb + 2 * j],
                                                  stg[r * 20 + cb + 2 * j + 1]);
                    const int grow = bm0 + wm + mi * 16 + r;
                    const int gcol = wn + ni * 16 + cb;
                    __half* dst;
                    if (OMODE == 2) {              // q/k head-split [bh, t, d]
                        const int b = grow >> 11, tt = grow & 2047;
                        dst = Cp + ((size_t)((b << 4) + (bn0 >> 7)) * SEQ + tt) * DH + gcol;
                    } else {
                        dst = Cp + coff + (size_t)grow * ldc + bn0 + gcol;
                    }
                    *reinterpret_cast<uint4*>(dst) = *reinterpret_cast<uint4*>(hv);
                }
                __syncwarp();
            }
    }
}

// ------ FA2-style fused attention: register softmax, mma.sync, dbl-buf K/V ----
constexpr int AQP = 136;                       // Q/K pitch (halves)
constexpr int AVP = 72;                        // V pitch (halves)
constexpr int KSTG = 64 * AQP * 2;             // 17408
constexpr int VSTG = 128 * AVP * 2;            // 18432
constexpr int OFF_K = 128 * AQP * 2;           // 34816 (after Q)
constexpr int OFF_V = OFF_K + 2 * KSTG;        // 69632
constexpr int SMEM_ATT = OFF_V + 2 * VSTG;     // 106496

__global__ void __launch_bounds__(256, 2)
attn_reg128(const __half* __restrict__ qh,   // [bh, t, d]
            const __half* __restrict__ kh,   // [bh, s, d] (pre-scaled)
            const __half* __restrict__ vp,   // [bh, d, s]
            float* __restrict__ ctx)         // [b, t, E] normalized fp32
{
    extern __shared__ __align__(128) char smem[];
    __half* Qs = (__half*)smem;

    const int bh = blockIdx.x & 31;
    const int qt = 15 - (blockIdx.x >> 5);     // heavy q-tiles first
    const int b = bh >> 4, h = bh & 15;
    const int tid  = threadIdx.x;
    const int wid  = tid >> 5;
    const int lane = tid & 31;
    const int nkt = 2 * qt + 2;

    auto load_kv = [&](int kt, int st) {       // K 64x128 + V 128x64 into stage st
        const __half* kg = kh + ((size_t)bh * SEQ + kt * 64) * DH;
        const __half* vg = vp + (size_t)bh * DH * SEQ + kt * 64;
        char* Kst = smem + OFF_K + st * KSTG;
        char* Vst = smem + OFF_V + st * VSTG;
        #pragma unroll
        for (int i = 0; i < 4; i++) {
            int s = i * 256 + tid;
            int rk = s >> 4, ck = s & 15;
            uint32_t dk = smem_u32(Kst + (rk * AQP + ck * 8) * 2);
            asm volatile("cp.async.cg.shared.global [%0], [%1], 16;"
                         :: "r"(dk), "l"(kg + (size_t)rk * DH + ck * 8));
            int rv = s >> 3, cv = s & 7;
            uint32_t dv = smem_u32(Vst + (rv * AVP + cv * 8) * 2);
            asm volatile("cp.async.cg.shared.global [%0], [%1], 16;"
                         :: "r"(dv), "l"(vg + (size_t)rv * SEQ + cv * 8));
        }
    };

    // prologue group 1: Q + KV(0) stage 0
    {
        const __half* qg = qh + ((size_t)bh * SEQ + qt * 128) * DH;
        #pragma unroll
        for (int i = 0; i < 8; i++) {
            int s = i * 256 + tid;
            int row = s >> 4, seg = s & 15;
            uint32_t dst = smem_u32(Qs + row * AQP + seg * 8);
            asm volatile("cp.async.cg.shared.global [%0], [%1], 16;"
                         :: "r"(dst), "l"(qg + (size_t)row * DH + seg * 8));
        }
        load_kv(0, 0);
        asm volatile("cp.async.commit_group;" ::: "memory");
    }
    // prologue group 2: KV(1) stage 1
    if (nkt > 1) load_kv(1, 1);
    asm volatile("cp.async.commit_group;" ::: "memory");

    float oacc[16][4];
    #pragma unroll
    for (int n = 0; n < 16; n++)
        #pragma unroll
        for (int e = 0; e < 4; e++) oacc[n][e] = 0.0f;
    float rsum0 = 0.0f, rsum1 = 0.0f;

    const uint32_t qbase = smem_u32(Qs + (wid * 16 + (lane & 15)) * AQP + (lane >> 4) * 8);
    const int frow = ((lane >> 4) << 3) + (lane & 7);      // fragment row
    const int fcol = ((lane >> 3) & 1) * 8;                // fragment col offset
    const int r0g = qt * 128 + wid * 16 + (lane >> 2);     // global q row (c0,c1)
    const int ce  = (lane & 3) * 2;                        // col-in-tile even index

    for (int kt = 0; kt < nkt; kt++) {
        asm volatile("cp.async.wait_group 1;" ::: "memory");   // KV(kt) landed
        __syncthreads();
        const int st = kt & 1;
        const uint32_t kbase = smem_u32(smem + OFF_K + st * KSTG) + (uint32_t)(frow * AQP + fcol) * 2;
        const uint32_t vbase = smem_u32(smem + OFF_V + st * VSTG) + (uint32_t)(frow * AVP + fcol) * 2;

        // ---- S = Q @ K^T : 8 private 16x8 accumulators ----
        float sacc[8][4];
        #pragma unroll
        for (int n = 0; n < 8; n++)
            #pragma unroll
            for (int e = 0; e < 4; e++) sacc[n][e] = 0.0f;
        #pragma unroll
        for (int kk = 0; kk < 8; kk++) {
            uint32_t a0, a1, a2, a3;
            ldsm4(a0, a1, a2, a3, qbase + (uint32_t)(kk * 16) * 2);
            #pragma unroll
            for (int np = 0; np < 4; np++) {
                uint32_t b0, b1, b2, b3;
                ldsm4(b0, b1, b2, b3, kbase + (uint32_t)(np * 16 * AQP + kk * 16) * 2);
                mma16816(sacc[2 * np],     a0, a1, a2, a3, b0, b1);
                mma16816(sacc[2 * np + 1], a0, a1, a2, a3, b2, b3);
            }
        }

        // ---- exp (+ causal mask only on diagonal tiles) + rowsum -> P frags ----
        uint32_t pa[16];
        if (kt < 2 * qt) {                        // interior tile: mask provably dead
            #pragma unroll
            for (int n = 0; n < 8; n++) {
                float s0 = __expf(sacc[n][0]);
                float s1 = __expf(sacc[n][1]);
                float s2 = __expf(sacc[n][2]);
                float s3 = __expf(sacc[n][3]);
                rsum0 += s0 + s1;
                rsum1 += s2 + s3;
                __half2 h01 = __floats2half2_rn(s0, s1);
                __half2 h23 = __floats2half2_rn(s2, s3);
                pa[n * 2]     = *reinterpret_cast<uint32_t*>(&h01);
                pa[n * 2 + 1] = *reinterpret_cast<uint32_t*>(&h23);
            }
        } else {                                   // diagonal tile: apply causal mask
            #pragma unroll
            for (int n = 0; n < 8; n++) {
                const int colb = kt * 64 + n * 8 + ce;
                float s0 = (colb     <= r0g)     ? __expf(sacc[n][0]) : 0.0f;
                float s1 = (colb + 1 <= r0g)     ? __expf(sacc[n][1]) : 0.0f;
                float s2 = (colb     <= r0g + 8) ? __expf(sacc[n][2]) : 0.0f;
                float s3 = (colb + 1 <= r0g + 8) ? __expf(sacc[n][3]) : 0.0f;
                rsum0 += s0 + s1;
                rsum1 += s2 + s3;
                __half2 h01 = __floats2half2_rn(s0, s1);
                __half2 h23 = __floats2half2_rn(s2, s3);
                pa[n * 2]     = *reinterpret_cast<uint32_t*>(&h01);
                pa[n * 2 + 1] = *reinterpret_cast<uint32_t*>(&h23);
            }
        }

        // ---- O += P @ V^T (A = P fragments, layout identity) ----
        #pragma unroll
        for (int j = 0; j < 4; j++) {
            const uint32_t a0 = pa[4 * j], a1 = pa[4 * j + 1];
            const uint32_t a2 = pa[4 * j + 2], a3 = pa[4 * j + 3];
            #pragma unroll
            for (int dp = 0; dp < 8; dp++) {
                uint32_t b0, b1, b2, b3;
                ldsm4(b0, b1, b2, b3, vbase + (uint32_t)(dp * 16 * AVP + j * 16) * 2);
                mma16816(oacc[2 * dp],     a0, a1, a2, a3, b0, b1);
                mma16816(oacc[2 * dp + 1], a0, a1, a2, a3, b2, b3);
            }
        }
        __syncthreads();                          // all warps done with stage st
        if (kt + 2 < nkt) load_kv(kt + 2, st);    // prefetch into freed stage
        asm volatile("cp.async.commit_group;" ::: "memory");
    }

    // ---- normalize and write ctx[b, t, h*DH + d] ----
    rsum0 += __shfl_xor_sync(0xffffffffu, rsum0, 1);
    rsum0 += __shfl_xor_sync(0xffffffffu, rsum0, 2);
    rsum1 += __shfl_xor_sync(0xffffffffu, rsum1, 1);
    rsum1 += __shfl_xor_sync(0xffffffffu, rsum1, 2);
    const float inv0 = 1.0f / rsum0;
    const float inv1 = 1.0f / rsum1;
    float* base0 = ctx + ((size_t)(b * SEQ + r0g)) * EMB + h * DH + ce;
    float* base1 = base0 + (size_t)8 * EMB;
    #pragma unroll
    for (int dn = 0; dn < 16; dn++) {
        float2 v0 = make_float2(oacc[dn][0] * inv0, oacc[dn][1] * inv0);
        float2 v1 = make_float2(oacc[dn][2] * inv1, oacc[dn][3] * inv1);
        *reinterpret_cast<float2*>(base0 + dn * 8) = v0;
        *reinterpret_cast<float2*>(base1 + dn * 8) = v1;
    }
}

// ---------------- block reductions ----------------
__device__ __forceinline__ float blk_sum(float v) {
    __shared__ float sh_s[32];
    __shared__ float tot_s;
    int lane = threadIdx.x & 31, w = threadIdx.x >> 5;
    #pragma unroll
    for (int o = 16; o; o >>= 1) v += __shfl_xor_sync(0xffffffffu, v, o);
    if (lane == 0) sh_s[w] = v;
    __syncthreads();
    if (threadIdx.x == 0) {
        float r = 0.f; int nw = blockDim.x >> 5;
        for (int i = 0; i < nw; i++) r += sh_s[i];
        tot_s = r;
    }
    __syncthreads();
    float r = tot_s;
    __syncthreads();
    return r;
}

// ---------------- conversions / norms ----------------
__global__ void f2h_k(const float* __restrict__ in, __half* __restrict__ out) {
    const int stride = gridDim.x * blockDim.x * 4;
    int base = (blockIdx.x * blockDim.x + threadIdx.x) * 4;
    #pragma unroll
    for (int r = 0; r < 4; r++) {
        int i = base + r * stride;
        float4 v = *reinterpret_cast<const float4*>(in + i);
        __half2 h[2];
        h[0] = __floats2half2_rn(v.x, v.y);
        h[1] = __floats2half2_rn(v.z, v.w);
        *reinterpret_cast<uint2*>(out + i) = *reinterpret_cast<uint2*>(h);
    }
}

struct W7 { const float* p[7]; };
__global__ void f2h7_k(W7 ws, __half* __restrict__ out) {
    const int plane = blockIdx.y;
    const float* in = ws.p[plane];
    __half* o = out + (size_t)plane * EMB * EMB;
    const int stride = gridDim.x * blockDim.x * 4;
    int base = (blockIdx.x * blockDim.x + threadIdx.x) * 4;
    #pragma unroll
    for (int r = 0; r < 4; r++) {
        int i = base + r * stride;
        float4 v = *reinterpret_cast<const float4*>(in + i);
        __half2 h[2];
        h[0] = __floats2half2_rn(v.x, v.y);
        h[1] = __floats2half2_rn(v.z, v.w);
        *reinterpret_cast<uint2*>(o + i) = *reinterpret_cast<uint2*>(h);
    }
}

__global__ void layernorm_h(const float* __restrict__ in, __half* __restrict__ out,
                            const float* __restrict__ g, const float* __restrict__ b) {
    const float* row = in + (size_t)blockIdx.x * EMB;
    __half* orow = out + (size_t)blockIdx.x * EMB;
    __shared__ float buf[EMB];
    float s = 0.f;
    for (int i = threadIdx.x; i < EMB; i += blockDim.x) { float v = row[i]; buf[i] = v; s += v; }
    const float mu = blk_sum(s) * (1.0f / EMB);
    float sq = 0.f;
    for (int i = threadIdx.x; i < EMB; i += blockDim.x) { float d = buf[i] - mu; sq += d * d; }
    const float var = blk_sum(sq) * (1.0f / EMB);
    const float inv = rsqrtf(var + 1e-5f);
    for (int i = threadIdx.x; i < EMB; i += blockDim.x)
        orow[i] = __float2half_rn((buf[i] - mu) * inv * g[i] + b[i]);
}

// x := rmsnorm(x) (fp32, residual base) and xh := half(x)
__global__ void rmsnorm_dual(float* __restrict__ x, __half* __restrict__ xh,
                             const float* __restrict__ g) {
    float* row = x + (size_t)blockIdx.x * EMB;
    __half* orow = xh + (size_t)blockIdx.x * EMB;
    __shared__ float buf[EMB];
    float ss = 0.f;
    for (int i = threadIdx.x; i < EMB; i += blockDim.x) { float v = row[i]; buf[i] = v; ss += v * v; }
    ss = blk_sum(ss);
    const float sc = rsqrtf(ss * (1.0f / EMB) + 1e-6f);
    for (int i = threadIdx.x; i < EMB; i += blockDim.x) {
        float r = g[i] * buf[i] * sc;
        row[i] = r;
        orow[i] = __float2half_rn(r);
    }
}

// out = x2 + mlp_rms_g * g * rsqrt(mean(g^2)+eps),  g = w*sigmoid(beta*w)*u  (half w,u)
__global__ void final_k(const float* __restrict__ x2, const __half* __restrict__ wv,
                        const __half* __restrict__ uv, const float* __restrict__ beta,
                        const float* __restrict__ gamma, float* __restrict__ out) {
    const size_t r = blockIdx.x;
    const float bet = beta[0];
    const __half* wrow = wv + r * EMB;
    const __half* urow = uv + r * EMB;
    __shared__ float buf[EMB];
    float ss = 0.f;
    for (int i = threadIdx.x; i < EMB; i += blockDim.x) {
        float wq = __half2float(wrow[i]);
        float s = 1.0f / (1.0f + __expf(-bet * wq));
        float gq = wq * s * __half2float(urow[i]);
        buf[i] = gq; ss += gq * gq;
    }
    ss = blk_sum(ss);
    const float sc = rsqrtf(ss * (1.0f / EMB) + 1e-6f);
    for (int i = threadIdx.x; i < EMB; i += blockDim.x)
        out[r * EMB + i] = x2[r * EMB + i] + gamma[i] * buf[i] * sc;
}

// ---------------- launcher ----------------
extern "C" void kernel_launch(void* const* d_in, const int* in_sizes, int n_in,
                              void* d_out, int out_size) {
    const float* x     = (const float*)d_in[0];
    const float* Wq    = (const float*)d_in[1];
    const float* Wk    = (const float*)d_in[2];
    const float* Wv    = (const float*)d_in[3];
    const float* Wo    = (const float*)d_in[4];
    const float* ln_g  = (const float*)d_in[5];
    const float* ln_b  = (const float*)d_in[6];
    const float* rms_g = (const float*)d_in[7];
    const float* W0    = (const float*)d_in[8];
    const float* swW   = (const float*)d_in[9];
    const float* swV   = (const float*)d_in[10];
    const float* swb   = (const float*)d_in[11];
    const float* mrg   = (const float*)d_in[12];
    float* out = (float*)d_out;

    __half *xh, *wh, *qkv, *vp, *cth, *x2h, *hh, *wuh;
    float *ctx, *xa;
    cudaGetSymbolAddress((void**)&xh,   g_xh);
    cudaGetSymbolAddress((void**)&wh,   g_wh);
    cudaGetSymbolAddress((void**)&qkv,  g_qkvh);
    cudaGetSymbolAddress((void**)&vp,   g_vp);
    cudaGetSymbolAddress((void**)&ctx,  g_ctx);
    cudaGetSymbolAddress((void**)&cth,  g_cth);
    cudaGetSymbolAddress((void**)&xa,   g_xa);
    cudaGetSymbolAddress((void**)&x2h,  g_x2h);
    cudaGetSymbolAddress((void**)&hh,   g_hh);
    cudaGetSymbolAddress((void**)&wuh,  g_wuh);

    __half* qh = qkv + 0 * PLANE;
    __half* kh = qkv + 1 * PLANE;
    __half* wvh = wuh + 0 * PLANE;
    __half* uvh = wuh + 1 * PLANE;
    const long long NW = (long long)EMB * EMB;

    cudaFuncSetAttribute(gemm_h<2,false>, cudaFuncAttributeMaxDynamicSharedMemorySize, SMEM_GEMM);
    cudaFuncSetAttribute(gemm_h<0,true >, cudaFuncAttributeMaxDynamicSharedMemorySize, SMEM_GEMM);
    cudaFuncSetAttribute(gemm_h<1,false>, cudaFuncAttributeMaxDynamicSharedMemorySize, SMEM_GEMM);
    cudaFuncSetAttribute(attn_reg128,     cudaFuncAttributeMaxDynamicSharedMemorySize, SMEM_ATT);

    const float scale = 0.08838834764831845f;  // 1/sqrt(128)
    const int NEW = MTOT * EMB;                // 8,388,608
    dim3 blk(256);

    // fp32 -> fp16 operand conversions (ILP-4 grid-stride)
    f2h_k<<<NEW / 4096, 256>>>(x, xh);
    W7 ws; ws.p[0]=Wq; ws.p[1]=Wk; ws.p[2]=Wv; ws.p[3]=Wo; ws.p[4]=W0; ws.p[5]=swW; ws.p[6]=swV;
    f2h7_k<<<dim3(NW / 4096, 7), 256>>>(ws, wh);

    // merged QKV projection: z=0 q head-split, z=1 k scaled head-split,
    // z=2 v transposed straight into vp (repack fused)
    dim3 gqkv(EMB / BN, MTOT / BM, 3);         // (16,32,3)
    gemm_h<2,false><<<gqkv, blk, SMEM_GEMM>>>(32,
        xh, EMB, 0, wh, EMB, EMB, nullptr, qkv, EMB, vp, nullptr, 1.0f, scale, 0);

    // FA2-style fused attention (register softmax), normalized fp32 ctx
    attn_reg128<<<512, blk, SMEM_ATT>>>(qh, kh, vp, ctx);

    layernorm_h<<<MTOT, 256>>>(ctx, cth, ln_g, ln_b);

    // xa = x + cth @ Wo^T (fp32, residual fused via accumulator init)
    dim3 gp(EMB / BN, MTOT / BM, 1);           // (16,32,1)
    gemm_h<0,true><<<gp, blk, SMEM_GEMM>>>(32,
        cth, EMB, 0, wh + 3 * NW, EMB, 0, xa, nullptr, EMB, nullptr, x, 1.0f, 1.0f, 0);

    rmsnorm_dual<<<MTOT, 256>>>(xa, x2h, rms_g);

    // h = x2 @ W0^T (half out)
    gemm_h<1,false><<<gp, blk, SMEM_GEMM>>>(32,
        x2h, EMB, 0, wh + 4 * NW, EMB, 0, nullptr, hh, EMB, nullptr, nullptr, 1.0f, 1.0f, 0);

    // merged swW/swV: z selects weight plane + half output plane
    dim3 gsw(EMB / BN, MTOT / BM, 2);          // (16,32,2)
    gemm_h<1,false><<<gsw, blk, SMEM_GEMM>>>(32,
        hh, EMB, 0, wh + 5 * NW, EMB, EMB, nullptr, wuh, EMB, nullptr, nullptr, 1.0f, 1.0f,
        (long long)PLANE);

    final_k<<<MTOT, 256>>>(xa, wvh, uvh, swb, mrg, out);   // swiglu + rmsnorm + residual
}

// round 17
// speedup vs baseline: 1.2320x; 1.0166x over previous
#include <cuda_runtime.h>
#include <cuda_fp16.h>
#include <mma.h>
#include <cstdint>

using namespace nvcuda;

#define SEQ 2048
#define EMB 2048
#define NB  2
#define NH  16
#define DH  128
#define MTOT (NB*SEQ)   // 4096
#define PLANE ((size_t)MTOT*EMB)

// ---------------- scratch (static device globals) ----------------
__device__ __half g_xh  [MTOT*EMB];
__device__ __half g_wh  [7][EMB*EMB];       // wq,wk,wv,wo,w0,sww,swv (contiguous)
__device__ __half g_qkvh[2][MTOT*EMB];      // plane0: qh [bh,t,d]; 1: kh [bh,s,d]
__device__ __half g_vp  [MTOT*EMB];         // [bh, d, s] (written by QKV epilogue)
__device__ float  g_ctx [MTOT*EMB];         // attention output (normalized fp32)
__device__ __half g_cth [MTOT*EMB];
__device__ float  g_xa  [MTOT*EMB];
__device__ __half g_x2h [MTOT*EMB];
__device__ __half g_hh  [MTOT*EMB];
__device__ __half g_wuh [2][MTOT*EMB];      // plane0: w, plane1: u (fp16)

__device__ __forceinline__ uint32_t smem_u32(const void* p) {
    uint32_t a;
    asm("{ .reg .u64 t; cvta.to.shared.u64 t, %1; cvt.u32.u64 %0, t; }" : "=r"(a) : "l"(p));
    return a;
}
__device__ __forceinline__ void ldsm4(uint32_t& r0, uint32_t& r1, uint32_t& r2, uint32_t& r3,
                                      uint32_t addr) {
    asm volatile("ldmatrix.sync.aligned.m8n8.x4.shared.b16 {%0,%1,%2,%3}, [%4];"
                 : "=r"(r0), "=r"(r1), "=r"(r2), "=r"(r3) : "r"(addr));
}
__device__ __forceinline__ void mma16816(float* c, uint32_t a0, uint32_t a1, uint32_t a2,
                                         uint32_t a3, uint32_t b0, uint32_t b1) {
    asm volatile("mma.sync.aligned.m16n8k16.row.col.f32.f16.f16.f32 "
                 "{%0,%1,%2,%3}, {%4,%5,%6,%7}, {%8,%9}, {%0,%1,%2,%3};"
                 : "+f"(c[0]), "+f"(c[1]), "+f"(c[2]), "+f"(c[3])
                 : "r"(a0), "r"(a1), "r"(a2), "r"(a3), "r"(b0), "r"(b1));
}

// ------------- fp16 wmma NT GEMM, BK=64 chunks, 3-stage cp.async ------------
constexpr int BM = 128, BN = 128, PITCH = 72;          // 64 + 8 pad (halves)
constexpr int STG_BYTES   = BM * PITCH * 2;            // 18432 per operand
constexpr int STAGE_BYTES = 2 * STG_BYTES;             // 36864 (A+B)
constexpr int NSTG = 3;
constexpr int SMEM_GEMM   = NSTG * STAGE_BYTES;        // 110592

// OMODE: 0 = fp32 out (opt RES); 1 = half plain out; 2 = QKV combined
//   (z=0 q head-split, z=1 k head-split scaled, z=2 v transposed into Vp)
template<int OMODE, bool RES>
__global__ void __launch_bounds__(256, 2)
gemm_h(int nk,  // number of 64-wide k-chunks
       const __half* __restrict__ A, int lda, int zRowA,
       const __half* __restrict__ B, int ldb, int zRowB,
       float* __restrict__ C, __half* __restrict__ Ch, int ldc,
       __half* __restrict__ Vp,
       const float* __restrict__ Rres, float alphaA, float alphaB,
       long long sC)
{
    const int bn0 = blockIdx.x * BN;
    const int bm0 = blockIdx.y * BM;
    const int z = blockIdx.z;

    extern __shared__ __align__(128) char smem[];
    const int tid  = threadIdx.x;
    const int wid  = tid >> 5;
    const int lane = tid & 31;
    const int wm = (wid & 3) * 32;
    const int wn = (wid >> 2) * 64;

    const __half* Abase = A + (size_t)(z * zRowA + bm0) * lda;
    const __half* Bbase = B + (size_t)(z * zRowB + bn0) * ldb;
    const long long coff = (long long)z * sC;

    auto load_chunk = [&](int kc) {
        const int st = kc % NSTG;
        char* sA = smem + st * STAGE_BYTES;
        char* sB = sA + STG_BYTES;
        const __half* ag = Abase + kc * 64;
        const __half* bg = Bbase + kc * 64;
        #pragma unroll
        for (int i = 0; i < 4; i++) {            // 1024 16B segs per operand
            int idx = i * 256 + tid;
            int row = idx >> 3, seg = idx & 7;
            uint32_t da = smem_u32(sA + row * (PITCH * 2) + seg * 16);
            const __half* srca = ag + (size_t)row * lda + seg * 8;
            asm volatile("cp.async.cg.shared.global [%0], [%1], 16;" :: "r"(da), "l"(srca));
            uint32_t db = smem_u32(sB + row * (PITCH * 2) + seg * 16);
            const __half* srcb = bg + (size_t)row * ldb + seg * 8;
            asm volatile("cp.async.cg.shared.global [%0], [%1], 16;" :: "r"(db), "l"(srcb));
        }
        asm volatile("cp.async.commit_group;" ::: "memory");
    };

    wmma::fragment<wmma::accumulator, 16, 16, 16, float> acc[2][4];
    #pragma unroll
    for (int mi = 0; mi < 2; mi++)
        #pragma unroll
        for (int ni = 0; ni < 4; ni++) {
            if (RES)
                wmma::load_matrix_sync(acc[mi][ni],
                    Rres + coff + (long long)(bm0 + wm + mi * 16) * ldc + (bn0 + wn + ni * 16),
                    ldc, wmma::mem_row_major);
            else
                wmma::fill_fragment(acc[mi][ni], 0.0f);
        }

    load_chunk(0);
    if (nk > 1) load_chunk(1);

    for (int kc = 0; kc < nk; kc++) {
        if (kc + 1 < nk)
            asm volatile("cp.async.wait_group 1;" ::: "memory");
        else
            asm volatile("cp.async.wait_group 0;" ::: "memory");
        __syncthreads();                          // single sync per 64-chunk

        const __half* sA = (const __half*)(smem + (kc % NSTG) * STAGE_BYTES);
        const __half* sB = sA + BM * PITCH;

        // rolling double-buffered fragments over 4 kk sub-steps
        wmma::fragment<wmma::matrix_a, 16, 16, 16, __half, wmma::row_major> af[2][2];
        wmma::fragment<wmma::matrix_b, 16, 16, 16, __half, wmma::col_major> bf[2][4];

        // load kk=0 -> buf0
        #pragma unroll
        for (int mi = 0; mi < 2; mi++)
            wmma::load_matrix_sync(af[0][mi], sA + (wm + mi * 16) * PITCH, PITCH);
        #pragma unroll
        for (int j = 0; j < 4; j++)
            wmma::load_matrix_sync(bf[0][j], sB + (wn + j * 16) * PITCH, PITCH);

        if (kc + 2 < nk) load_chunk(kc + 2);      // gmem prefetch (3rd stage)

        #pragma unroll
        for (int kk = 0; kk < 4; kk++) {
            const int cur = kk & 1;
            const int nxt = cur ^ 1;
            if (kk + 1 < 4) {                     // load kk+1 -> other buffer
                #pragma unroll
                for (int mi = 0; mi < 2; mi++)
                    wmma::load_matrix_sync(af[nxt][mi],
                        sA + (wm + mi * 16) * PITCH + (kk + 1) * 16, PITCH);
                #pragma unroll
                for (int j = 0; j < 4; j++)
                    wmma::load_matrix_sync(bf[nxt][j],
                        sB + (wn + j * 16) * PITCH + (kk + 1) * 16, PITCH);
            }
            #pragma unroll
            for (int mi = 0; mi < 2; mi++)
                #pragma unroll
                for (int j = 0; j < 4; j++)
                    wmma::mma_sync(acc[mi][j], af[cur][mi], bf[cur][j], acc[mi][j]);
        }
    }

    const float alpha = (OMODE == 2) ? ((z == 1) ? alphaB : alphaA) : alphaA;
    if (alpha != 1.0f) {
        #pragma unroll
        for (int mi = 0; mi < 2; mi++)
            #pragma unroll
            for (int ni = 0; ni < 4; ni++)
                #pragma unroll
                for (int e = 0; e < acc[mi][ni].num_elements; e++)
                    acc[mi][ni].x[e] *= alpha;
    }

    if (OMODE == 0) {
        float* Cp = C + coff;
        #pragma unroll
        for (int mi = 0; mi < 2; mi++)
            #pragma unroll
            for (int ni = 0; ni < 4; ni++)
                wmma::store_matrix_sync(
                    Cp + (long long)(bm0 + wm + mi * 16) * ldc + (bn0 + wn + ni * 16),
                    acc[mi][ni], ldc, wmma::mem_row_major);
    } else {
        __syncthreads();                          // all MMAs done before smem reuse
        float* stg = (float*)smem + wid * 320;    // 16x16 tile, pitch 20
        __half* Cp = (OMODE == 2) ? (Ch + (size_t)z * PLANE) : Ch;
        const bool vmode = (OMODE == 2) && (z == 2);
        #pragma unroll
        for (int mi = 0; mi < 2; mi++)
            #pragma unroll
            for (int ni = 0; ni < 4; ni++) {
                wmma::store_matrix_sync(stg, acc[mi][ni], 20, wmma::mem_row_major);
                __syncwarp();
                if (vmode) {
                    // tile = 16 tokens x 16 heads at fixed d; transpose to vp[bh][d][s]
                    const int c  = lane >> 1;      // head within tile
                    const int hf = lane & 1;       // token half (8 each)
                    __half hv8[8];
                    #pragma unroll
                    for (int rr = 0; rr < 8; rr++)
                        hv8[rr] = __float2half_rn(stg[(hf * 8 + rr) * 20 + c]);
                    const int grow0 = bm0 + wm + mi * 16;
                    const int bb = grow0 >> 11, t0 = grow0 & 2047;
                    const int d = (bn0 + wn + ni * 16) >> 4;
                    __half* dstv = Vp + ((size_t)((bb << 4) + c) * DH + d) * SEQ + t0 + hf * 8;
                    *reinterpret_cast<uint4*>(dstv) = *reinterpret_cast<uint4*>(hv8);
                } else {
                    const int r  = lane >> 1;
                    const int cb = (lane & 1) * 8;
                    __half2 hv[4];
                    #pragma unroll
                    for (int j = 0; j < 4; j++)
                        hv[j] = __floats2half2_rn(stg[r * 20 + cb + 2 * j],
                                                  stg[r * 20 + cb + 2 * j + 1]);
                    const int grow = bm0 + wm + mi * 16 + r;
                    const int gcol = wn + ni * 16 + cb;
                    __half* dst;
                    if (OMODE == 2) {              // q/k head-split [bh, t, d]
                        const int b = grow >> 11, tt = grow & 2047;
                        dst = Cp + ((size_t)((b << 4) + (bn0 >> 7)) * SEQ + tt) * DH + gcol;
                    } else {
                        dst = Cp + coff + (size_t)grow * ldc + bn0 + gcol;
                    }
                    *reinterpret_cast<uint4*>(dst) = *reinterpret_cast<uint4*>(hv);
                }
                __syncwarp();
            }
    }
}

// ------ FA2-style fused attention: register softmax, mma.sync, dbl-buf K/V ----
constexpr int AQP = 136;                       // Q/K pitch (halves)
constexpr int AVP = 72;                        // V pitch (halves)
constexpr int KSTG = 64 * AQP * 2;             // 17408
constexpr int VSTG = 128 * AVP * 2;            // 18432
constexpr int OFF_K = 128 * AQP * 2;           // 34816 (after Q)
constexpr int OFF_V = OFF_K + 2 * KSTG;        // 69632
constexpr int SMEM_ATT = OFF_V + 2 * VSTG;     // 106496

__global__ void __launch_bounds__(256, 2)
attn_reg128(const __half* __restrict__ qh,   // [bh, t, d]
            const __half* __restrict__ kh,   // [bh, s, d] (pre-scaled)
            const __half* __restrict__ vp,   // [bh, d, s]
            float* __restrict__ ctx)         // [b, t, E] normalized fp32
{
    extern __shared__ __align__(128) char smem[];
    __half* Qs = (__half*)smem;

    const int bh = blockIdx.x & 31;
    const int qt = 15 - (blockIdx.x >> 5);     // heavy q-tiles first
    const int b = bh >> 4, h = bh & 15;
    const int tid  = threadIdx.x;
    const int wid  = tid >> 5;
    const int lane = tid & 31;
    const int nkt = 2 * qt + 2;

    auto load_kv = [&](int kt, int st) {       // K 64x128 + V 128x64 into stage st
        const __half* kg = kh + ((size_t)bh * SEQ + kt * 64) * DH;
        const __half* vg = vp + (size_t)bh * DH * SEQ + kt * 64;
        char* Kst = smem + OFF_K + st * KSTG;
        char* Vst = smem + OFF_V + st * VSTG;
        #pragma unroll
        for (int i = 0; i < 4; i++) {
            int s = i * 256 + tid;
            int rk = s >> 4, ck = s & 15;
            uint32_t dk = smem_u32(Kst + (rk * AQP + ck * 8) * 2);
            asm volatile("cp.async.cg.shared.global [%0], [%1], 16;"
                         :: "r"(dk), "l"(kg + (size_t)rk * DH + ck * 8));
            int rv = s >> 3, cv = s & 7;
            uint32_t dv = smem_u32(Vst + (rv * AVP + cv * 8) * 2);
            asm volatile("cp.async.cg.shared.global [%0], [%1], 16;"
                         :: "r"(dv), "l"(vg + (size_t)rv * SEQ + cv * 8));
        }
    };

    // prologue group 1: Q + KV(0) stage 0
    {
        const __half* qg = qh + ((size_t)bh * SEQ + qt * 128) * DH;
        #pragma unroll
        for (int i = 0; i < 8; i++) {
            int s = i * 256 + tid;
            int row = s >> 4, seg = s & 15;
            uint32_t dst = smem_u32(Qs + row * AQP + seg * 8);
            asm volatile("cp.async.cg.shared.global [%0], [%1], 16;"
                         :: "r"(dst), "l"(qg + (size_t)row * DH + seg * 8));
        }
        load_kv(0, 0);
        asm volatile("cp.async.commit_group;" ::: "memory");
    }
    // prologue group 2: KV(1) stage 1
    if (nkt > 1) load_kv(1, 1);
    asm volatile("cp.async.commit_group;" ::: "memory");

    float oacc[16][4];
    #pragma unroll
    for (int n = 0; n < 16; n++)
        #pragma unroll
        for (int e = 0; e < 4; e++) oacc[n][e] = 0.0f;
    float rsum0 = 0.0f, rsum1 = 0.0f;

    const uint32_t qbase = smem_u32(Qs + (wid * 16 + (lane & 15)) * AQP + (lane >> 4) * 8);
    const int frow = ((lane >> 4) << 3) + (lane & 7);      // fragment row
    const int fcol = ((lane >> 3) & 1) * 8;                // fragment col offset
    const int r0g = qt * 128 + wid * 16 + (lane >> 2);     // global q row (c0,c1)
    const int ce  = (lane & 3) * 2;                        // col-in-tile even index

    for (int kt = 0; kt < nkt; kt++) {
        asm volatile("cp.async.wait_group 1;" ::: "memory");   // KV(kt) landed
        __syncthreads();
        const int st = kt & 1;
        const uint32_t kbase = smem_u32(smem + OFF_K + st * KSTG) + (uint32_t)(frow * AQP + fcol) * 2;
        const uint32_t vbase = smem_u32(smem + OFF_V + st * VSTG) + (uint32_t)(frow * AVP + fcol) * 2;

        // ---- S = Q @ K^T : 8 private 16x8 accumulators ----
        float sacc[8][4];
        #pragma unroll
        for (int n = 0; n < 8; n++)
            #pragma unroll
            for (int e = 0; e < 4; e++) sacc[n][e] = 0.0f;
        #pragma unroll
        for (int kk = 0; kk < 8; kk++) {
            uint32_t a0, a1, a2, a3;
            ldsm4(a0, a1, a2, a3, qbase + (uint32_t)(kk * 16) * 2);
            #pragma unroll
            for (int np = 0; np < 4; np++) {
                uint32_t b0, b1, b2, b3;
                ldsm4(b0, b1, b2, b3, kbase + (uint32_t)(np * 16 * AQP + kk * 16) * 2);
                mma16816(sacc[2 * np],     a0, a1, a2, a3, b0, b1);
                mma16816(sacc[2 * np + 1], a0, a1, a2, a3, b2, b3);
            }
        }

        // ---- exp (+ causal mask only on diagonal tiles) + rowsum -> P frags ----
        uint32_t pa[16];
        if (kt < 2 * qt) {                        // interior tile: mask provably dead
            #pragma unroll
            for (int n = 0; n < 8; n++) {
                float s0 = __expf(sacc[n][0]);
                float s1 = __expf(sacc[n][1]);
                float s2 = __expf(sacc[n][2]);
                float s3 = __expf(sacc[n][3]);
                rsum0 += s0 + s1;
                rsum1 += s2 + s3;
                __half2 h01 = __floats2half2_rn(s0, s1);
                __half2 h23 = __floats2half2_rn(s2, s3);
                pa[n * 2]     = *reinterpret_cast<uint32_t*>(&h01);
                pa[n * 2 + 1] = *reinterpret_cast<uint32_t*>(&h23);
            }
        } else {                                   // diagonal tile: apply causal mask
            #pragma unroll
            for (int n = 0; n < 8; n++) {
                const int colb = kt * 64 + n * 8 + ce;
                float s0 = (colb     <= r0g)     ? __expf(sacc[n][0]) : 0.0f;
                float s1 = (colb + 1 <= r0g)     ? __expf(sacc[n][1]) : 0.0f;
                float s2 = (colb     <= r0g + 8) ? __expf(sacc[n][2]) : 0.0f;
                float s3 = (colb + 1 <= r0g + 8) ? __expf(sacc[n][3]) : 0.0f;
                rsum0 += s0 + s1;
                rsum1 += s2 + s3;
                __half2 h01 = __floats2half2_rn(s0, s1);
                __half2 h23 = __floats2half2_rn(s2, s3);
                pa[n * 2]     = *reinterpret_cast<uint32_t*>(&h01);
                pa[n * 2 + 1] = *reinterpret_cast<uint32_t*>(&h23);
            }
        }

        // ---- O += P @ V^T (A = P fragments, layout identity) ----
        #pragma unroll
        for (int j = 0; j < 4; j++) {
            const uint32_t a0 = pa[4 * j], a1 = pa[4 * j + 1];
            const uint32_t a2 = pa[4 * j + 2], a3 = pa[4 * j + 3];
            #pragma unroll
            for (int dp = 0; dp < 8; dp++) {
                uint32_t b0, b1, b2, b3;
                ldsm4(b0, b1, b2, b3, vbase + (uint32_t)(dp * 16 * AVP + j * 16) * 2);
                mma16816(oacc[2 * dp],     a0, a1, a2, a3, b0, b1);
                mma16816(oacc[2 * dp + 1], a0, a1, a2, a3, b2, b3);
            }
        }
        __syncthreads();                          // all warps done with stage st
        if (kt + 2 < nkt) load_kv(kt + 2, st);    // prefetch into freed stage
        asm volatile("cp.async.commit_group;" ::: "memory");
    }

    // ---- normalize and write ctx[b, t, h*DH + d] ----
    rsum0 += __shfl_xor_sync(0xffffffffu, rsum0, 1);
    rsum0 += __shfl_xor_sync(0xffffffffu, rsum0, 2);
    rsum1 += __shfl_xor_sync(0xffffffffu, rsum1, 1);
    rsum1 += __shfl_xor_sync(0xffffffffu, rsum1, 2);
    const float inv0 = 1.0f / rsum0;
    const float inv1 = 1.0f / rsum1;
    float* base0 = ctx + ((size_t)(b * SEQ + r0g)) * EMB + h * DH + ce;
    float* base1 = base0 + (size_t)8 * EMB;
    #pragma unroll
    for (int dn = 0; dn < 16; dn++) {
        float2 v0 = make_float2(oacc[dn][0] * inv0, oacc[dn][1] * inv0);
        float2 v1 = make_float2(oacc[dn][2] * inv1, oacc[dn][3] * inv1);
        *reinterpret_cast<float2*>(base0 + dn * 8) = v0;
        *reinterpret_cast<float2*>(base1 + dn * 8) = v1;
    }
}

// ---------------- block reductions ----------------
__device__ __forceinline__ float blk_sum(float v) {
    __shared__ float sh_s[32];
    __shared__ float tot_s;
    int lane = threadIdx.x & 31, w = threadIdx.x >> 5;
    #pragma unroll
    for (int o = 16; o; o >>= 1) v += __shfl_xor_sync(0xffffffffu, v, o);
    if (lane == 0) sh_s[w] = v;
    __syncthreads();
    if (threadIdx.x == 0) {
        float r = 0.f; int nw = blockDim.x >> 5;
        for (int i = 0; i < nw; i++) r += sh_s[i];
        tot_s = r;
    }
    __syncthreads();
    float r = tot_s;
    __syncthreads();
    return r;
}

// ---------------- conversions / norms (512 threads, register-resident) -------
__global__ void f2h_k(const float* __restrict__ in, __half* __restrict__ out) {
    const int stride = gridDim.x * blockDim.x * 4;
    int base = (blockIdx.x * blockDim.x + threadIdx.x) * 4;
    #pragma unroll
    for (int r = 0; r < 4; r++) {
        int i = base + r * stride;
        float4 v = *reinterpret_cast<const float4*>(in + i);
        __half2 h[2];
        h[0] = __floats2half2_rn(v.x, v.y);
        h[1] = __floats2half2_rn(v.z, v.w);
        *reinterpret_cast<uint2*>(out + i) = *reinterpret_cast<uint2*>(h);
    }
}

struct W7 { const float* p[7]; };
__global__ void f2h7_k(W7 ws, __half* __restrict__ out) {
    const int plane = blockIdx.y;
    const float* in = ws.p[plane];
    __half* o = out + (size_t)plane * EMB * EMB;
    const int stride = gridDim.x * blockDim.x * 4;
    int base = (blockIdx.x * blockDim.x + threadIdx.x) * 4;
    #pragma unroll
    for (int r = 0; r < 4; r++) {
        int i = base + r * stride;
        float4 v = *reinterpret_cast<const float4*>(in + i);
        __half2 h[2];
        h[0] = __floats2half2_rn(v.x, v.y);
        h[1] = __floats2half2_rn(v.z, v.w);
        *reinterpret_cast<uint2*>(o + i) = *reinterpret_cast<uint2*>(h);
    }
}

// 512 threads: each owns one float4 of the row (registers; no smem buffer)
__global__ void __launch_bounds__(512)
layernorm_h(const float* __restrict__ in, __half* __restrict__ out,
            const float* __restrict__ g, const float* __restrict__ b) {
    const int c = threadIdx.x * 4;
    const float4 v = *reinterpret_cast<const float4*>(in + (size_t)blockIdx.x * EMB + c);
    const float mu = blk_sum(v.x + v.y + v.z + v.w) * (1.0f / EMB);
    const float dx = v.x - mu, dy = v.y - mu, dz = v.z - mu, dw = v.w - mu;
    const float var = blk_sum(dx * dx + dy * dy + dz * dz + dw * dw) * (1.0f / EMB);
    const float inv = rsqrtf(var + 1e-5f);
    const float4 gv = *reinterpret_cast<const float4*>(g + c);
    const float4 bv = *reinterpret_cast<const float4*>(b + c);
    __half2 h[2];
    h[0] = __floats2half2_rn(dx * inv * gv.x + bv.x, dy * inv * gv.y + bv.y);
    h[1] = __floats2half2_rn(dz * inv * gv.z + bv.z, dw * inv * gv.w + bv.w);
    *reinterpret_cast<uint2*>(out + (size_t)blockIdx.x * EMB + c) = *reinterpret_cast<uint2*>(h);
}

// x := rmsnorm(x) (fp32, residual base) and xh := half(x); 512 threads
__global__ void __launch_bounds__(512)
rmsnorm_dual(float* __restrict__ x, __half* __restrict__ xh,
             const float* __restrict__ g) {
    const int c = threadIdx.x * 4;
    float* row = x + (size_t)blockIdx.x * EMB;
    const float4 v = *reinterpret_cast<const float4*>(row + c);
    const float ss = blk_sum(v.x * v.x + v.y * v.y + v.z * v.z + v.w * v.w);
    const float sc = rsqrtf(ss * (1.0f / EMB) + 1e-6f);
    const float4 gv = *reinterpret_cast<const float4*>(g + c);
    float4 r;
    r.x = gv.x * v.x * sc; r.y = gv.y * v.y * sc;
    r.z = gv.z * v.z * sc; r.w = gv.w * v.w * sc;
    *reinterpret_cast<float4*>(row + c) = r;
    __half2 h[2];
    h[0] = __floats2half2_rn(r.x, r.y);
    h[1] = __floats2half2_rn(r.z, r.w);
    *reinterpret_cast<uint2*>(xh + (size_t)blockIdx.x * EMB + c) = *reinterpret_cast<uint2*>(h);
}

// out = x2 + mlp_rms_g * gq * rsqrt(mean(gq^2)+eps), gq = w*sigmoid(beta*w)*u; 512 thr
__global__ void __launch_bounds__(512)
final_k(const float* __restrict__ x2, const __half* __restrict__ wv,
        const __half* __restrict__ uv, const float* __restrict__ beta,
        const float* __restrict__ gamma, float* __restrict__ out) {
    const int c = threadIdx.x * 4;
    const size_t off = (size_t)blockIdx.x * EMB + c;
    const float bet = beta[0];
    uint2 wp = *reinterpret_cast<const uint2*>(wv + off);
    uint2 up = *reinterpret_cast<const uint2*>(uv + off);
    float2 w01 = __half22float2(*reinterpret_cast<__half2*>(&wp.x));
    float2 w23 = __half22float2(*reinterpret_cast<__half2*>(&wp.y));
    float2 u01 = __half22float2(*reinterpret_cast<__half2*>(&up.x));
    float2 u23 = __half22float2(*reinterpret_cast<__half2*>(&up.y));
    float gq[4];
    gq[0] = w01.x * (1.0f / (1.0f + __expf(-bet * w01.x))) * u01.x;
    gq[1] = w01.y * (1.0f / (1.0f + __expf(-bet * w01.y))) * u01.y;
    gq[2] = w23.x * (1.0f / (1.0f + __expf(-bet * w23.x))) * u23.x;
    gq[3] = w23.y * (1.0f / (1.0f + __expf(-bet * w23.y))) * u23.y;
    const float ss = blk_sum(gq[0] * gq[0] + gq[1] * gq[1] + gq[2] * gq[2] + gq[3] * gq[3]);
    const float sc = rsqrtf(ss * (1.0f / EMB) + 1e-6f);
    const float4 x2v = *reinterpret_cast<const float4*>(x2 + off);
    const float4 gm  = *reinterpret_cast<const float4*>(gamma + c);
    float4 o;
    o.x = x2v.x + gm.x * gq[0] * sc;
    o.y = x2v.y + gm.y * gq[1] * sc;
    o.z = x2v.z + gm.z * gq[2] * sc;
    o.w = x2v.w + gm.w * gq[3] * sc;
    *reinterpret_cast<float4*>(out + off) = o;
}

// ---------------- launcher ----------------
extern "C" void kernel_launch(void* const* d_in, const int* in_sizes, int n_in,
                              void* d_out, int out_size) {
    const float* x     = (const float*)d_in[0];
    const float* Wq    = (const float*)d_in[1];
    const float* Wk    = (const float*)d_in[2];
    const float* Wv    = (const float*)d_in[3];
    const float* Wo    = (const float*)d_in[4];
    const float* ln_g  = (const float*)d_in[5];
    const float* ln_b  = (const float*)d_in[6];
    const float* rms_g = (const float*)d_in[7];
    const float* W0    = (const float*)d_in[8];
    const float* swW   = (const float*)d_in[9];
    const float* swV   = (const float*)d_in[10];
    const float* swb   = (const float*)d_in[11];
    const float* mrg   = (const float*)d_in[12];
    float* out = (float*)d_out;

    __half *xh, *wh, *qkv, *vp, *cth, *x2h, *hh, *wuh;
    float *ctx, *xa;
    cudaGetSymbolAddress((void**)&xh,   g_xh);
    cudaGetSymbolAddress((void**)&wh,   g_wh);
    cudaGetSymbolAddress((void**)&qkv,  g_qkvh);
    cudaGetSymbolAddress((void**)&vp,   g_vp);
    cudaGetSymbolAddress((void**)&ctx,  g_ctx);
    cudaGetSymbolAddress((void**)&cth,  g_cth);
    cudaGetSymbolAddress((void**)&xa,   g_xa);
    cudaGetSymbolAddress((void**)&x2h,  g_x2h);
    cudaGetSymbolAddress((void**)&hh,   g_hh);
    cudaGetSymbolAddress((void**)&wuh,  g_wuh);

    __half* qh = qkv + 0 * PLANE;
    __half* kh = qkv + 1 * PLANE;
    __half* wvh = wuh + 0 * PLANE;
    __half* uvh = wuh + 1 * PLANE;
    const long long NW = (long long)EMB * EMB;

    cudaFuncSetAttribute(gemm_h<2,false>, cudaFuncAttributeMaxDynamicSharedMemorySize, SMEM_GEMM);
    cudaFuncSetAttribute(gemm_h<0,true >, cudaFuncAttributeMaxDynamicSharedMemorySize, SMEM_GEMM);
    cudaFuncSetAttribute(gemm_h<1,false>, cudaFuncAttributeMaxDynamicSharedMemorySize, SMEM_GEMM);
    cudaFuncSetAttribute(attn_reg128,     cudaFuncAttributeMaxDynamicSharedMemorySize, SMEM_ATT);

    const float scale = 0.08838834764831845f;  // 1/sqrt(128)
    const int NEW = MTOT * EMB;                // 8,388,608
    dim3 blk(256);

    // fp32 -> fp16 operand conversions (ILP-4 grid-stride)
    f2h_k<<<NEW / 4096, 256>>>(x, xh);
    W7 ws; ws.p[0]=Wq; ws.p[1]=Wk; ws.p[2]=Wv; ws.p[3]=Wo; ws.p[4]=W0; ws.p[5]=swW; ws.p[6]=swV;
    f2h7_k<<<dim3(NW / 4096, 7), 256>>>(ws, wh);

    // merged QKV projection: z=0 q head-split, z=1 k scaled head-split,
    // z=2 v transposed straight into vp (repack fused)
    dim3 gqkv(EMB / BN, MTOT / BM, 3);         // (16,32,3)
    gemm_h<2,false><<<gqkv, blk, SMEM_GEMM>>>(32,
        xh, EMB, 0, wh, EMB, EMB, nullptr, qkv, EMB, vp, nullptr, 1.0f, scale, 0);

    // FA2-style fused attention (register softmax), normalized fp32 ctx
    attn_reg128<<<512, blk, SMEM_ATT>>>(qh, kh, vp, ctx);

    layernorm_h<<<MTOT, 512>>>(ctx, cth, ln_g, ln_b);

    // xa = x + cth @ Wo^T (fp32, residual fused via accumulator init)
    dim3 gp(EMB / BN, MTOT / BM, 1);           // (16,32,1)
    gemm_h<0,true><<<gp, blk, SMEM_GEMM>>>(32,
        cth, EMB, 0, wh + 3 * NW, EMB, 0, xa, nullptr, EMB, nullptr, x, 1.0f, 1.0f, 0);

    rmsnorm_dual<<<MTOT, 512>>>(xa, x2h, rms_g);

    // h = x2 @ W0^T (half out)
    gemm_h<1,false><<<gp, blk, SMEM_GEMM>>>(32,
        x2h, EMB, 0, wh + 4 * NW, EMB, 0, nullptr, hh, EMB, nullptr, nullptr, 1.0f, 1.0f, 0);

    // merged swW/swV: z selects weight plane + half output plane
    dim3 gsw(EMB / BN, MTOT / BM, 2);          // (16,32,2)
    gemm_h<1,false><<<gsw, blk, SMEM_GEMM>>>(32,
        hh, EMB, 0, wh + 5 * NW, EMB, EMB, nullptr, wuh, EMB, nullptr, nullptr, 1.0f, 1.0f,
        (long long)PLANE);

    final_k<<<MTOT, 512>>>(xa, wvh, uvh, swb, mrg, out);   // swiglu + rmsnorm + residual
}